// round 2
// baseline (speedup 1.0000x reference)
#include <cuda_runtime.h>
#include <cuda_bf16.h>
#include <math.h>

#define N_NODES 25000
#define E_EDGES 250000
#define DD 128

// ---------------- scratch (device globals; no allocation allowed) ----------
__device__ float2 g_dn[(size_t)N_NODES * DD];        // (denom, numerator)
__device__ float  g_mid[(size_t)N_NODES * DD];       // agg + x
__device__ float  g_h1[(size_t)N_NODES * 2 * DD];    // after first MLP linear
__device__ float  g_h[(size_t)N_NODES * DD];         // after second MLP linear
__device__ float  g_bnsum[2 * DD];
__device__ float  g_bnsq[2 * DD];
__device__ float  g_bnscale[2 * DD];
__device__ float  g_bnshift[2 * DD];

// ---------------- init ------------------------------------------------------
__global__ void init_kernel() {
    int i = blockIdx.x * 256 + threadIdx.x;
    if (i < N_NODES * DD) g_dn[i] = make_float2(0.f, 0.f);
    if (i < 2 * DD) { g_bnsum[i] = 0.f; g_bnsq[i] = 0.f; }
}

// ---------------- edge MLP: gather-GEMM + bias + ReLU + LN + residual -------
// e = LN(relu(cat(x[row],x[col],edge_attr) @ W_e + b_e)) + edge_attr
__global__ __launch_bounds__(256, 1)
void edge_mlp_kernel(const float* __restrict__ x,
                     const float* __restrict__ edge_attr,
                     const int* __restrict__ erow, const int* __restrict__ ecol,
                     const float* __restrict__ W_e, const float* __restrict__ b_e,
                     const float* __restrict__ g_e, const float* __restrict__ be_e,
                     float* __restrict__ e_out)
{
    extern __shared__ float sm[];
    float* As = sm;              // GEMM phase: [128][128] stride 128; LN phase: stride 129
    float* Bs = sm + 128 * 129;  // [128][128]
    const int tid = threadIdx.x;
    const int e0 = blockIdx.x * 128;
    const int m0 = (tid >> 4) << 3;
    const int n0 = (tid & 15) << 3;

    float acc[8][8];
#pragma unroll
    for (int i = 0; i < 8; ++i)
#pragma unroll
        for (int j = 0; j < 8; ++j) acc[i][j] = 0.f;

    for (int ch = 0; ch < 3; ++ch) {
        // A tile: gathered rows (warp-per-row, coalesced 512B)
#pragma unroll 4
        for (int j = tid; j < 128 * 32; j += 256) {
            int m = j >> 5, k4 = j & 31;
            int eid = e0 + m; if (eid >= E_EDGES) eid = E_EDGES - 1;
            float4 v;
            if (ch == 0)      v = ((const float4*)x)[(size_t)erow[eid] * 32 + k4];
            else if (ch == 1) v = ((const float4*)x)[(size_t)ecol[eid] * 32 + k4];
            else              v = ((const float4*)edge_attr)[(size_t)eid * 32 + k4];
            *((float4*)(As + m * 128 + k4 * 4)) = v;
        }
        // B tile: W_e chunk (stays L2-resident across blocks)
#pragma unroll 4
        for (int j = tid; j < 128 * 32; j += 256) {
            int k = j >> 5, n4 = j & 31;
            *((float4*)(Bs + k * 128 + n4 * 4)) =
                ((const float4*)W_e)[(size_t)(ch * 128 + k) * 32 + n4];
        }
        __syncthreads();
#pragma unroll 2
        for (int k = 0; k < 128; ++k) {
            float a[8];
#pragma unroll
            for (int i = 0; i < 8; ++i) a[i] = As[(m0 + i) * 128 + k];
            float4 bv0 = *(const float4*)(Bs + k * 128 + n0);
            float4 bv1 = *(const float4*)(Bs + k * 128 + n0 + 4);
            float b[8] = {bv0.x, bv0.y, bv0.z, bv0.w, bv1.x, bv1.y, bv1.z, bv1.w};
#pragma unroll
            for (int i = 0; i < 8; ++i)
#pragma unroll
                for (int j = 0; j < 8; ++j) acc[i][j] = fmaf(a[i], b[j], acc[i][j]);
        }
        __syncthreads();
    }
    // bias + relu -> As (stride 129, conflict-free per-row reads)
#pragma unroll
    for (int i = 0; i < 8; ++i)
#pragma unroll
        for (int j = 0; j < 8; ++j)
            As[(m0 + i) * 129 + n0 + j] = fmaxf(acc[i][j] + b_e[n0 + j], 0.f);
    __syncthreads();
    // LayerNorm per edge + residual
    if (tid < 128) {
        int eid = e0 + tid;
        if (eid < E_EDGES) {
            const float* hrow = As + tid * 129;
            float s = 0.f, ss = 0.f;
#pragma unroll 8
            for (int c = 0; c < 128; ++c) { float v = hrow[c]; s += v; ss += v * v; }
            float mu = s * (1.f / 128.f);
            float var = ss * (1.f / 128.f) - mu * mu;
            float rstd = rsqrtf(var + 1e-5f);
#pragma unroll 4
            for (int c = 0; c < 128; ++c) {
                float v = (hrow[c] - mu) * rstd * g_e[c] + be_e[c]
                          + edge_attr[(size_t)eid * 128 + c];
                e_out[(size_t)eid * 128 + c] = v;
            }
        }
    }
}

// ---------------- softmax aggregation (single pass, float2 RED) -------------
// msg > 0 and bounded, so exp(msg*t) needs no max-subtraction (same result).
__global__ void agg_pass_kernel(const float* __restrict__ x, const float* __restrict__ e,
                                const int* __restrict__ erow, const int* __restrict__ ecol,
                                const float* __restrict__ t_ptr)
{
    const float t = *t_ptr;
    int idx = blockIdx.x * 256 + threadIdx.x;
    if (idx >= E_EDGES * DD) return;
    int eid = idx >> 7, c = idx & 127;
    int r = erow[eid], d = ecol[eid];
    float msg = fmaxf(x[(size_t)r * 128 + c] + e[idx], 0.f) + 1e-7f;
    float ex = __expf(msg * t);
    atomicAdd(&g_dn[(size_t)d * 128 + c], make_float2(ex, msg * ex));
}

__global__ void combine_kernel(const float* __restrict__ x) {
    int i = blockIdx.x * 256 + threadIdx.x;
    if (i >= N_NODES * DD) return;
    float2 dn = g_dn[i];
    float agg = (dn.x > 0.f) ? (dn.y / dn.x) : 0.f;
    g_mid[i] = x[i] + agg;
}

// ---------------- node MLP linear 1: [N,128] @ [128,256] + b ----------------
__global__ __launch_bounds__(256, 1)
void mlp1_kernel(const float* __restrict__ W_m1, const float* __restrict__ b_m1)
{
    extern __shared__ float sm[];
    float* As = sm;
    float* Bs = sm + 128 * 128;
    const int tid = threadIdx.x;
    const int r0 = blockIdx.x * 128;
    const int noff = blockIdx.y * 128;
    const int m0 = (tid >> 4) << 3;
    const int n0 = (tid & 15) << 3;
    float acc[8][8];
#pragma unroll
    for (int i = 0; i < 8; ++i)
#pragma unroll
        for (int j = 0; j < 8; ++j) acc[i][j] = 0.f;

#pragma unroll 4
    for (int j = tid; j < 128 * 32; j += 256) {
        int m = j >> 5, k4 = j & 31;
        int r = r0 + m; if (r >= N_NODES) r = N_NODES - 1;
        *((float4*)(As + m * 128 + k4 * 4)) = ((const float4*)g_mid)[(size_t)r * 32 + k4];
    }
#pragma unroll 4
    for (int j = tid; j < 128 * 32; j += 256) {
        int k = j >> 5, n4 = j & 31;
        *((float4*)(Bs + k * 128 + n4 * 4)) =
            ((const float4*)W_m1)[(size_t)k * 64 + (noff >> 2) + n4];
    }
    __syncthreads();
#pragma unroll 2
    for (int k = 0; k < 128; ++k) {
        float a[8];
#pragma unroll
        for (int i = 0; i < 8; ++i) a[i] = As[(m0 + i) * 128 + k];
        float4 bv0 = *(const float4*)(Bs + k * 128 + n0);
        float4 bv1 = *(const float4*)(Bs + k * 128 + n0 + 4);
        float b[8] = {bv0.x, bv0.y, bv0.z, bv0.w, bv1.x, bv1.y, bv1.z, bv1.w};
#pragma unroll
        for (int i = 0; i < 8; ++i)
#pragma unroll
            for (int j = 0; j < 8; ++j) acc[i][j] = fmaf(a[i], b[j], acc[i][j]);
    }
#pragma unroll
    for (int i = 0; i < 8; ++i) {
        int r = r0 + m0 + i;
        if (r < N_NODES) {
#pragma unroll
            for (int j = 0; j < 8; ++j)
                g_h1[(size_t)r * 256 + noff + n0 + j] = acc[i][j] + b_m1[noff + n0 + j];
        }
    }
}

// ---------------- BatchNorm stats (training-mode, biased var) ---------------
__global__ void bn_stats_kernel() {
    int c = threadIdx.x;          // 256 channels
    int r0 = blockIdx.x * 64;
    int rend = min(r0 + 64, N_NODES);
    float s = 0.f, ss = 0.f;
    for (int r = r0; r < rend; ++r) {
        float v = g_h1[(size_t)r * 256 + c];
        s += v; ss += v * v;
    }
    atomicAdd(&g_bnsum[c], s);
    atomicAdd(&g_bnsq[c], ss);
}

__global__ void bn_finalize_kernel(const float* __restrict__ g_bn,
                                   const float* __restrict__ b_bn) {
    int c = threadIdx.x;
    float mean = g_bnsum[c] * (1.f / N_NODES);
    float var = g_bnsq[c] * (1.f / N_NODES) - mean * mean;
    float rstd = rsqrtf(var + 1e-5f);
    float a = rstd * g_bn[c];
    g_bnscale[c] = a;
    g_bnshift[c] = b_bn[c] - mean * a;
}

// ---------------- node MLP linear 2 with fused BN+ReLU on A-load ------------
__global__ __launch_bounds__(256, 1)
void mlp2_kernel(const float* __restrict__ W_m2, const float* __restrict__ b_m2)
{
    extern __shared__ float sm[];
    float* As = sm;
    float* Bs = sm + 128 * 128;
    float* sc = sm + 2 * 128 * 128;
    float* sh = sc + 256;
    const int tid = threadIdx.x;
    sc[tid] = g_bnscale[tid];
    sh[tid] = g_bnshift[tid];
    const int r0 = blockIdx.x * 128;
    const int m0 = (tid >> 4) << 3;
    const int n0 = (tid & 15) << 3;
    float acc[8][8];
#pragma unroll
    for (int i = 0; i < 8; ++i)
#pragma unroll
        for (int j = 0; j < 8; ++j) acc[i][j] = 0.f;
    __syncthreads();   // sc/sh visible

    for (int cc = 0; cc < 2; ++cc) {
#pragma unroll 4
        for (int j = tid; j < 128 * 32; j += 256) {
            int m = j >> 5, k4 = j & 31;
            int r = r0 + m; if (r >= N_NODES) r = N_NODES - 1;
            float4 v = ((const float4*)g_h1)[(size_t)r * 64 + cc * 32 + k4];
            int kk = cc * 128 + k4 * 4;
            v.x = fmaxf(v.x * sc[kk]     + sh[kk],     0.f);
            v.y = fmaxf(v.y * sc[kk + 1] + sh[kk + 1], 0.f);
            v.z = fmaxf(v.z * sc[kk + 2] + sh[kk + 2], 0.f);
            v.w = fmaxf(v.w * sc[kk + 3] + sh[kk + 3], 0.f);
            *((float4*)(As + m * 128 + k4 * 4)) = v;
        }
#pragma unroll 4
        for (int j = tid; j < 128 * 32; j += 256) {
            int k = j >> 5, n4 = j & 31;
            *((float4*)(Bs + k * 128 + n4 * 4)) =
                ((const float4*)W_m2)[(size_t)(cc * 128 + k) * 32 + n4];
        }
        __syncthreads();
#pragma unroll 2
        for (int k = 0; k < 128; ++k) {
            float a[8];
#pragma unroll
            for (int i = 0; i < 8; ++i) a[i] = As[(m0 + i) * 128 + k];
            float4 bv0 = *(const float4*)(Bs + k * 128 + n0);
            float4 bv1 = *(const float4*)(Bs + k * 128 + n0 + 4);
            float b[8] = {bv0.x, bv0.y, bv0.z, bv0.w, bv1.x, bv1.y, bv1.z, bv1.w};
#pragma unroll
            for (int i = 0; i < 8; ++i)
#pragma unroll
                for (int j = 0; j < 8; ++j) acc[i][j] = fmaf(a[i], b[j], acc[i][j]);
        }
        __syncthreads();
    }
#pragma unroll
    for (int i = 0; i < 8; ++i) {
        int r = r0 + m0 + i;
        if (r < N_NODES) {
#pragma unroll
            for (int j = 0; j < 8; ++j)
                g_h[(size_t)r * 128 + n0 + j] = acc[i][j] + b_m2[n0 + j];
        }
    }
}

// ---------------- MessageNorm + residual + node LayerNorm -------------------
__device__ __forceinline__ float breduce(float v, float* sb) {
#pragma unroll
    for (int o = 16; o > 0; o >>= 1) v += __shfl_down_sync(0xffffffffu, v, o);
    if ((threadIdx.x & 31) == 0) sb[threadIdx.x >> 5] = v;
    __syncthreads();
    float r = sb[0] + sb[1] + sb[2] + sb[3];
    __syncthreads();
    return r;
}

__global__ __launch_bounds__(128)
void node_out_kernel(const float* __restrict__ x, const float* __restrict__ scale_ptr,
                     const float* __restrict__ g_n, const float* __restrict__ b_n,
                     float* __restrict__ xout)
{
    __shared__ float sb[4];
    int node = blockIdx.x;
    int c = threadIdx.x;
    float hv = g_h[(size_t)node * 128 + c];
    float xv = x[(size_t)node * 128 + c];
    float hn = sqrtf(breduce(hv * hv, sb));
    float xn = sqrtf(breduce(xv * xv, sb));
    float r = xv + hv / fmaxf(hn, 1e-12f) * xn * (*scale_ptr);
    float mu = breduce(r, sb) * (1.f / 128.f);
    float dv = r - mu;
    float var = breduce(dv * dv, sb) * (1.f / 128.f);
    xout[(size_t)node * 128 + c] = dv * rsqrtf(var + 1e-5f) * g_n[c] + b_n[c];
}

// ---------------- launch ----------------------------------------------------
extern "C" void kernel_launch(void* const* d_in, const int* in_sizes, int n_in,
                              void* d_out, int out_size)
{
    const float* x        = (const float*)d_in[0];
    const float* edge_attr= (const float*)d_in[1];
    const int*   eidx     = (const int*)  d_in[2];
    const float* W_e      = (const float*)d_in[3];
    const float* b_e      = (const float*)d_in[4];
    const float* g_e      = (const float*)d_in[5];
    const float* be_e     = (const float*)d_in[6];
    const float* t        = (const float*)d_in[7];
    const float* W_m1     = (const float*)d_in[8];
    const float* b_m1     = (const float*)d_in[9];
    const float* g_bn     = (const float*)d_in[10];
    const float* b_bn     = (const float*)d_in[11];
    const float* W_m2     = (const float*)d_in[12];
    const float* b_m2     = (const float*)d_in[13];
    const float* scale    = (const float*)d_in[14];
    const float* g_n      = (const float*)d_in[15];
    const float* b_n      = (const float*)d_in[16];
    const int* erow = eidx;
    const int* ecol = eidx + E_EDGES;
    float* xout  = (float*)d_out;
    float* e_out = (float*)d_out + (size_t)N_NODES * DD;   // output order: (x_out, e)

    const int smem_edge = (128 * 129 + 128 * 128) * 4;
    const int smem_gemm = 2 * 128 * 128 * 4;
    const int smem_gemm2 = (2 * 128 * 128 + 512) * 4;
    cudaFuncSetAttribute((const void*)edge_mlp_kernel,
                         cudaFuncAttributeMaxDynamicSharedMemorySize, smem_edge);
    cudaFuncSetAttribute((const void*)mlp1_kernel,
                         cudaFuncAttributeMaxDynamicSharedMemorySize, smem_gemm);
    cudaFuncSetAttribute((const void*)mlp2_kernel,
                         cudaFuncAttributeMaxDynamicSharedMemorySize, smem_gemm2);

    init_kernel<<<(N_NODES * DD + 255) / 256, 256>>>();
    edge_mlp_kernel<<<(E_EDGES + 127) / 128, 256, smem_edge>>>(
        x, edge_attr, erow, ecol, W_e, b_e, g_e, be_e, e_out);
    agg_pass_kernel<<<(E_EDGES * DD + 255) / 256, 256>>>(x, e_out, erow, ecol, t);
    combine_kernel<<<(N_NODES * DD + 255) / 256, 256>>>(x);
    dim3 g1((N_NODES + 127) / 128, 2);
    mlp1_kernel<<<g1, 256, smem_gemm>>>(W_m1, b_m1);
    bn_stats_kernel<<<(N_NODES + 63) / 64, 256>>>();
    bn_finalize_kernel<<<1, 256>>>(g_bn, b_bn);
    mlp2_kernel<<<(N_NODES + 127) / 128, 256, smem_gemm2>>>(W_m2, b_m2);
    node_out_kernel<<<N_NODES, 128>>>(x, scale, g_n, b_n, xout);
}

// round 4
// speedup vs baseline: 1.3148x; 1.3148x over previous
#include <cuda_runtime.h>
#include <cuda_bf16.h>
#include <math.h>
#include <stdint.h>

#define N_NODES 25000
#define E_EDGES 250000
#define DD 128

// ---------------- scratch (device globals; no allocation allowed) ----------
__device__ float2 g_dn[(size_t)N_NODES * DD];        // (denom, numerator)
__device__ float  g_mid[(size_t)N_NODES * DD];       // agg + x
__device__ float  g_h1[(size_t)N_NODES * 2 * DD];    // after first MLP linear
__device__ float  g_h[(size_t)N_NODES * DD];         // after second MLP linear
__device__ float  g_bnsum[2 * DD];
__device__ float  g_bnsq[2 * DD];
__device__ float  g_bnscale[2 * DD];
__device__ float  g_bnshift[2 * DD];
// W_e^T split to bf16 hi/lo, padded rows: [6 chunks][128 n][72 k] bf16
#define KP 72
__device__ unsigned short g_Bh[6 * 128 * KP];
__device__ unsigned short g_Bl[6 * 128 * KP];

// ---------------- init ------------------------------------------------------
__global__ void init_kernel() {
    int i = blockIdx.x * 256 + threadIdx.x;
    if (i < N_NODES * DD) g_dn[i] = make_float2(0.f, 0.f);
    if (i < 2 * DD) { g_bnsum[i] = 0.f; g_bnsq[i] = 0.f; }
}

// ---------------- prep: W_e -> transposed, split, padded --------------------
// B[n][k] = W_e[k][n]; chunk c holds k in [c*64, (c+1)*64).
__global__ void prep_B_kernel(const float* __restrict__ W_e) {
    int i = blockIdx.x * 256 + threadIdx.x;
    if (i >= 384 * 128) return;
    int k = i >> 7, n = i & 127;
    float v = W_e[i];
    __nv_bfloat16 h = __float2bfloat16(v);
    float hv = __bfloat162float(h);
    __nv_bfloat16 l = __float2bfloat16(v - hv);
    int c = k >> 6, kk = k & 63;
    int idx = (c * 128 + n) * KP + kk;
    g_Bh[idx] = __bfloat16_as_ushort(h);
    g_Bl[idx] = __bfloat16_as_ushort(l);
}

// ---------------- edge MLP on HMMA (mma.sync bf16, split 3-term) ------------
// smem byte layout
#define SM_IDX  0          // erow_s[128], ecol_s[128]
#define SM_PAR  1024       // b_e | g_e | be_e  (384 floats)
#define SM_AHI  4096       // 128 x 72 bf16 = 18432 B
#define SM_ALO  (SM_AHI + 18432)
#define SM_BHI  (SM_ALO + 18432)
#define SM_BLO  (SM_BHI + 18432)
#define SM_ES   SM_AHI     // epilogue: 128 x 129 float (66048 B), overlaps A/B
#define SM_EDGE_TOTAL (SM_BLO + 18432)

__device__ __forceinline__ void mma_bf16(float* d, const uint32_t* a,
                                         uint32_t b0, uint32_t b1) {
    asm volatile(
        "mma.sync.aligned.m16n8k16.row.col.f32.bf16.bf16.f32 "
        "{%0,%1,%2,%3}, {%4,%5,%6,%7}, {%8,%9}, {%0,%1,%2,%3};"
        : "+f"(d[0]), "+f"(d[1]), "+f"(d[2]), "+f"(d[3])
        : "r"(a[0]), "r"(a[1]), "r"(a[2]), "r"(a[3]), "r"(b0), "r"(b1));
}

__global__ __launch_bounds__(256, 2)
void edge_mlp_tc(const float* __restrict__ x, const float* __restrict__ edge_attr,
                 const int* __restrict__ erow, const int* __restrict__ ecol,
                 const float* __restrict__ b_e, const float* __restrict__ g_e,
                 const float* __restrict__ be_e, float* __restrict__ e_out)
{
    extern __shared__ __align__(128) char smem[];
    const int tid = threadIdx.x, wid = tid >> 5, lane = tid & 31;
    const int e0 = blockIdx.x * 128;
    const int wm = wid >> 1;          // row group: 4 groups of 32
    const int wn = wid & 1;           // col group: 2 groups of 64

    int*   erow_s = (int*)(smem + SM_IDX);
    int*   ecol_s = erow_s + 128;
    float* par    = (float*)(smem + SM_PAR);

    if (tid < 128) {
        int eid = min(e0 + tid, E_EDGES - 1);
        erow_s[tid] = erow[eid];
        ecol_s[tid] = ecol[eid];
        par[tid]       = b_e[tid];
        par[128 + tid] = g_e[tid];
        par[256 + tid] = be_e[tid];
    }
    __syncthreads();

    uint32_t* Ahi = (uint32_t*)(smem + SM_AHI);
    uint32_t* Alo = (uint32_t*)(smem + SM_ALO);
    uint32_t* Bhi = (uint32_t*)(smem + SM_BHI);
    uint32_t* Blo = (uint32_t*)(smem + SM_BLO);
    const int SP = KP / 2;            // row stride in u32 = 36 (conflict-free)

    float acc[2][8][4];
#pragma unroll
    for (int mt = 0; mt < 2; ++mt)
#pragma unroll
        for (int nt = 0; nt < 8; ++nt)
#pragma unroll
            for (int q = 0; q < 4; ++q) acc[mt][nt][q] = 0.f;

    for (int c = 0; c < 6; ++c) {
        if (c) __syncthreads();       // previous chunk's mma reads done
        // ---- A tile: gather + split fp32->bf16 hi/lo (2 threads per row) ---
        {
            int row = tid >> 1, half = tid & 1;
            const float* src;
            int col0 = (c & 1) << 6;
            if (c < 2)      src = x + (size_t)erow_s[row] * 128 + col0;
            else if (c < 4) src = x + (size_t)ecol_s[row] * 128 + col0;
            else            src = edge_attr + (size_t)min(e0 + row, E_EDGES - 1) * 128 + col0;
            src += half * 32;
            int base = row * SP + half * 16;
#pragma unroll
            for (int i = 0; i < 8; ++i) {
                float4 v = ((const float4*)src)[i];
                __nv_bfloat16 h0 = __float2bfloat16(v.x), h1 = __float2bfloat16(v.y);
                __nv_bfloat16 h2 = __float2bfloat16(v.z), h3 = __float2bfloat16(v.w);
                __nv_bfloat16 l0 = __float2bfloat16(v.x - __bfloat162float(h0));
                __nv_bfloat16 l1 = __float2bfloat16(v.y - __bfloat162float(h1));
                __nv_bfloat16 l2 = __float2bfloat16(v.z - __bfloat162float(h2));
                __nv_bfloat16 l3 = __float2bfloat16(v.w - __bfloat162float(h3));
                Ahi[base + i * 2]     = (uint32_t)__bfloat16_as_ushort(h0) | ((uint32_t)__bfloat16_as_ushort(h1) << 16);
                Ahi[base + i * 2 + 1] = (uint32_t)__bfloat16_as_ushort(h2) | ((uint32_t)__bfloat16_as_ushort(h3) << 16);
                Alo[base + i * 2]     = (uint32_t)__bfloat16_as_ushort(l0) | ((uint32_t)__bfloat16_as_ushort(l1) << 16);
                Alo[base + i * 2 + 1] = (uint32_t)__bfloat16_as_ushort(l2) | ((uint32_t)__bfloat16_as_ushort(l3) << 16);
            }
        }
        // ---- B tile: verbatim copy of pre-split image (L2-hot) -------------
        {
            const uint32_t* sh = (const uint32_t*)g_Bh + c * (128 * SP);
            const uint32_t* sl = (const uint32_t*)g_Bl + c * (128 * SP);
#pragma unroll
            for (int j = tid; j < 128 * SP; j += 256) { Bhi[j] = sh[j]; Blo[j] = sl[j]; }
        }
        __syncthreads();
        // ---- 3-term MMA over this K-chunk ----------------------------------
#pragma unroll
        for (int term = 0; term < 3; ++term) {
            const uint32_t* As = (term == 2) ? Alo : Ahi;
            const uint32_t* Bs = (term == 1) ? Blo : Bhi;
#pragma unroll
            for (int ks = 0; ks < 4; ++ks) {
                const int kb = ks * 8;               // u32 units
                uint32_t a[2][4];
#pragma unroll
                for (int mt = 0; mt < 2; ++mt) {
                    int ar = wm * 32 + mt * 16 + (lane >> 2);
                    int ac = kb + (lane & 3);
                    a[mt][0] = As[ar * SP + ac];
                    a[mt][1] = As[(ar + 8) * SP + ac];
                    a[mt][2] = As[ar * SP + ac + 4];
                    a[mt][3] = As[(ar + 8) * SP + ac + 4];
                }
#pragma unroll
                for (int nt = 0; nt < 8; ++nt) {
                    int bn = wn * 64 + nt * 8 + (lane >> 2);
                    uint32_t b0 = Bs[bn * SP + kb + (lane & 3)];
                    uint32_t b1 = Bs[bn * SP + kb + (lane & 3) + 4];
                    mma_bf16(acc[0][nt], a[0], b0, b1);
                    mma_bf16(acc[1][nt], a[1], b0, b1);
                }
            }
        }
    }
    __syncthreads();                  // before reusing smem as Es

    // ---- store accumulators to Es[128][129] --------------------------------
    float* Es = (float*)(smem + SM_ES);
#pragma unroll
    for (int mt = 0; mt < 2; ++mt) {
        int r = wm * 32 + mt * 16 + (lane >> 2);
#pragma unroll
        for (int nt = 0; nt < 8; ++nt) {
            int cc = wn * 64 + nt * 8 + ((lane & 3) << 1);
            Es[r * 129 + cc]           = acc[mt][nt][0];
            Es[r * 129 + cc + 1]       = acc[mt][nt][1];
            Es[(r + 8) * 129 + cc]     = acc[mt][nt][2];
            Es[(r + 8) * 129 + cc + 1] = acc[mt][nt][3];
        }
    }
    __syncthreads();

    // ---- bias + ReLU + LayerNorm + residual, write e_out -------------------
    if (tid < 128) {
        int eid = e0 + tid;
        if (eid < E_EDGES) {
            const float* hrow = Es + tid * 129;
            float s = 0.f, ss = 0.f;
#pragma unroll 8
            for (int cc = 0; cc < 128; ++cc) {
                float v = fmaxf(hrow[cc] + par[cc], 0.f);
                s += v; ss += v * v;
            }
            float mu = s * (1.f / 128.f);
            float rstd = rsqrtf(ss * (1.f / 128.f) - mu * mu + 1e-5f);
#pragma unroll 4
            for (int cc = 0; cc < 128; ++cc) {
                float v = fmaxf(hrow[cc] + par[cc], 0.f);
                e_out[(size_t)eid * 128 + cc] =
                    (v - mu) * rstd * par[128 + cc] + par[256 + cc]
                    + edge_attr[(size_t)eid * 128 + cc];
            }
        }
    }
}

// ---------------- softmax aggregation (single pass, float2 RED) -------------
__global__ void agg_pass_kernel(const float* __restrict__ x, const float* __restrict__ e,
                                const int* __restrict__ erow, const int* __restrict__ ecol,
                                const float* __restrict__ t_ptr)
{
    const float t = *t_ptr;
    int idx = blockIdx.x * 256 + threadIdx.x;
    if (idx >= E_EDGES * DD) return;
    int eid = idx >> 7, c = idx & 127;
    int r = erow[eid], d = ecol[eid];
    float msg = fmaxf(x[(size_t)r * 128 + c] + e[idx], 0.f) + 1e-7f;
    float ex = __expf(msg * t);
    atomicAdd(&g_dn[(size_t)d * 128 + c], make_float2(ex, msg * ex));
}

__global__ void combine_kernel(const float* __restrict__ x) {
    int i = blockIdx.x * 256 + threadIdx.x;
    if (i >= N_NODES * DD) return;
    float2 dn = g_dn[i];
    float agg = (dn.x > 0.f) ? (dn.y / dn.x) : 0.f;
    g_mid[i] = x[i] + agg;
}

// ---------------- node MLP linear 1: [N,128] @ [128,256] + b ----------------
__global__ __launch_bounds__(256, 1)
void mlp1_kernel(const float* __restrict__ W_m1, const float* __restrict__ b_m1)
{
    extern __shared__ float sm[];
    float* As = sm;
    float* Bs = sm + 128 * 128;
    const int tid = threadIdx.x;
    const int r0 = blockIdx.x * 128;
    const int noff = blockIdx.y * 128;
    const int m0 = (tid >> 4) << 3;
    const int n0 = (tid & 15) << 3;
    float acc[8][8];
#pragma unroll
    for (int i = 0; i < 8; ++i)
#pragma unroll
        for (int j = 0; j < 8; ++j) acc[i][j] = 0.f;

#pragma unroll 4
    for (int j = tid; j < 128 * 32; j += 256) {
        int m = j >> 5, k4 = j & 31;
        int r = r0 + m; if (r >= N_NODES) r = N_NODES - 1;
        *((float4*)(As + m * 128 + k4 * 4)) = ((const float4*)g_mid)[(size_t)r * 32 + k4];
    }
#pragma unroll 4
    for (int j = tid; j < 128 * 32; j += 256) {
        int k = j >> 5, n4 = j & 31;
        *((float4*)(Bs + k * 128 + n4 * 4)) =
            ((const float4*)W_m1)[(size_t)k * 64 + (noff >> 2) + n4];
    }
    __syncthreads();
#pragma unroll 2
    for (int k = 0; k < 128; ++k) {
        float a[8];
#pragma unroll
        for (int i = 0; i < 8; ++i) a[i] = As[(m0 + i) * 128 + k];
        float4 bv0 = *(const float4*)(Bs + k * 128 + n0);
        float4 bv1 = *(const float4*)(Bs + k * 128 + n0 + 4);
        float b[8] = {bv0.x, bv0.y, bv0.z, bv0.w, bv1.x, bv1.y, bv1.z, bv1.w};
#pragma unroll
        for (int i = 0; i < 8; ++i)
#pragma unroll
            for (int j = 0; j < 8; ++j) acc[i][j] = fmaf(a[i], b[j], acc[i][j]);
    }
#pragma unroll
    for (int i = 0; i < 8; ++i) {
        int r = r0 + m0 + i;
        if (r < N_NODES) {
#pragma unroll
            for (int j = 0; j < 8; ++j)
                g_h1[(size_t)r * 256 + noff + n0 + j] = acc[i][j] + b_m1[noff + n0 + j];
        }
    }
}

// ---------------- BatchNorm stats (training-mode, biased var) ---------------
__global__ void bn_stats_kernel() {
    int c = threadIdx.x;
    int r0 = blockIdx.x * 64;
    int rend = min(r0 + 64, N_NODES);
    float s = 0.f, ss = 0.f;
    for (int r = r0; r < rend; ++r) {
        float v = g_h1[(size_t)r * 256 + c];
        s += v; ss += v * v;
    }
    atomicAdd(&g_bnsum[c], s);
    atomicAdd(&g_bnsq[c], ss);
}

__global__ void bn_finalize_kernel(const float* __restrict__ g_bn,
                                   const float* __restrict__ b_bn) {
    int c = threadIdx.x;
    float mean = g_bnsum[c] * (1.f / N_NODES);
    float var = g_bnsq[c] * (1.f / N_NODES) - mean * mean;
    float rstd = rsqrtf(var + 1e-5f);
    float a = rstd * g_bn[c];
    g_bnscale[c] = a;
    g_bnshift[c] = b_bn[c] - mean * a;
}

// ---------------- node MLP linear 2 with fused BN+ReLU on A-load ------------
__global__ __launch_bounds__(256, 1)
void mlp2_kernel(const float* __restrict__ W_m2, const float* __restrict__ b_m2)
{
    extern __shared__ float sm[];
    float* As = sm;
    float* Bs = sm + 128 * 128;
    float* sc = sm + 2 * 128 * 128;
    float* sh = sc + 256;
    const int tid = threadIdx.x;
    sc[tid] = g_bnscale[tid];
    sh[tid] = g_bnshift[tid];
    const int r0 = blockIdx.x * 128;
    const int m0 = (tid >> 4) << 3;
    const int n0 = (tid & 15) << 3;
    float acc[8][8];
#pragma unroll
    for (int i = 0; i < 8; ++i)
#pragma unroll
        for (int j = 0; j < 8; ++j) acc[i][j] = 0.f;
    __syncthreads();

    for (int cc = 0; cc < 2; ++cc) {
#pragma unroll 4
        for (int j = tid; j < 128 * 32; j += 256) {
            int m = j >> 5, k4 = j & 31;
            int r = r0 + m; if (r >= N_NODES) r = N_NODES - 1;
            float4 v = ((const float4*)g_h1)[(size_t)r * 64 + cc * 32 + k4];
            int kk = cc * 128 + k4 * 4;
            v.x = fmaxf(v.x * sc[kk]     + sh[kk],     0.f);
            v.y = fmaxf(v.y * sc[kk + 1] + sh[kk + 1], 0.f);
            v.z = fmaxf(v.z * sc[kk + 2] + sh[kk + 2], 0.f);
            v.w = fmaxf(v.w * sc[kk + 3] + sh[kk + 3], 0.f);
            *((float4*)(As + m * 128 + k4 * 4)) = v;
        }
#pragma unroll 4
        for (int j = tid; j < 128 * 32; j += 256) {
            int k = j >> 5, n4 = j & 31;
            *((float4*)(Bs + k * 128 + n4 * 4)) =
                ((const float4*)W_m2)[(size_t)(cc * 128 + k) * 32 + n4];
        }
        __syncthreads();
#pragma unroll 2
        for (int k = 0; k < 128; ++k) {
            float a[8];
#pragma unroll
            for (int i = 0; i < 8; ++i) a[i] = As[(m0 + i) * 128 + k];
            float4 bv0 = *(const float4*)(Bs + k * 128 + n0);
            float4 bv1 = *(const float4*)(Bs + k * 128 + n0 + 4);
            float b[8] = {bv0.x, bv0.y, bv0.z, bv0.w, bv1.x, bv1.y, bv1.z, bv1.w};
#pragma unroll
            for (int i = 0; i < 8; ++i)
#pragma unroll
                for (int j = 0; j < 8; ++j) acc[i][j] = fmaf(a[i], b[j], acc[i][j]);
        }
        __syncthreads();
    }
#pragma unroll
    for (int i = 0; i < 8; ++i) {
        int r = r0 + m0 + i;
        if (r < N_NODES) {
#pragma unroll
            for (int j = 0; j < 8; ++j)
                g_h[(size_t)r * 128 + n0 + j] = acc[i][j] + b_m2[n0 + j];
        }
    }
}

// ---------------- MessageNorm + residual + node LayerNorm -------------------
__device__ __forceinline__ float breduce(float v, float* sbuf) {
#pragma unroll
    for (int o = 16; o > 0; o >>= 1) v += __shfl_down_sync(0xffffffffu, v, o);
    if ((threadIdx.x & 31) == 0) sbuf[threadIdx.x >> 5] = v;
    __syncthreads();
    float r = sbuf[0] + sbuf[1] + sbuf[2] + sbuf[3];
    __syncthreads();
    return r;
}

__global__ __launch_bounds__(128)
void node_out_kernel(const float* __restrict__ x, const float* __restrict__ scale_ptr,
                     const float* __restrict__ g_n, const float* __restrict__ b_n,
                     float* __restrict__ xout)
{
    __shared__ float sbuf[4];
    int node = blockIdx.x;
    int c = threadIdx.x;
    float hv = g_h[(size_t)node * 128 + c];
    float xv = x[(size_t)node * 128 + c];
    float hn = sqrtf(breduce(hv * hv, sbuf));
    float xn = sqrtf(breduce(xv * xv, sbuf));
    float r = xv + hv / fmaxf(hn, 1e-12f) * xn * (*scale_ptr);
    float mu = breduce(r, sbuf) * (1.f / 128.f);
    float dv = r - mu;
    float var = breduce(dv * dv, sbuf) * (1.f / 128.f);
    xout[(size_t)node * 128 + c] = dv * rsqrtf(var + 1e-5f) * g_n[c] + b_n[c];
}

// ---------------- launch ----------------------------------------------------
extern "C" void kernel_launch(void* const* d_in, const int* in_sizes, int n_in,
                              void* d_out, int out_size)
{
    const float* x        = (const float*)d_in[0];
    const float* edge_attr= (const float*)d_in[1];
    const int*   eidx     = (const int*)  d_in[2];
    const float* W_e      = (const float*)d_in[3];
    const float* b_e      = (const float*)d_in[4];
    const float* g_e      = (const float*)d_in[5];
    const float* be_e     = (const float*)d_in[6];
    const float* t        = (const float*)d_in[7];
    const float* W_m1     = (const float*)d_in[8];
    const float* b_m1     = (const float*)d_in[9];
    const float* g_bn     = (const float*)d_in[10];
    const float* b_bn     = (const float*)d_in[11];
    const float* W_m2     = (const float*)d_in[12];
    const float* b_m2     = (const float*)d_in[13];
    const float* scale    = (const float*)d_in[14];
    const float* g_n      = (const float*)d_in[15];
    const float* b_n      = (const float*)d_in[16];
    const int* erow = eidx;
    const int* ecol = eidx + E_EDGES;
    float* xout  = (float*)d_out;
    float* e_out = (float*)d_out + (size_t)N_NODES * DD;

    const int smem_gemm  = 2 * 128 * 128 * 4;
    const int smem_gemm2 = (2 * 128 * 128 + 512) * 4;
    cudaFuncSetAttribute((const void*)edge_mlp_tc,
                         cudaFuncAttributeMaxDynamicSharedMemorySize, SM_EDGE_TOTAL);
    cudaFuncSetAttribute((const void*)mlp1_kernel,
                         cudaFuncAttributeMaxDynamicSharedMemorySize, smem_gemm);
    cudaFuncSetAttribute((const void*)mlp2_kernel,
                         cudaFuncAttributeMaxDynamicSharedMemorySize, smem_gemm2);

    init_kernel<<<(N_NODES * DD + 255) / 256, 256>>>();
    prep_B_kernel<<<(384 * 128 + 255) / 256, 256>>>(W_e);
    edge_mlp_tc<<<(E_EDGES + 127) / 128, 256, SM_EDGE_TOTAL>>>(
        x, edge_attr, erow, ecol, b_e, g_e, be_e, e_out);
    agg_pass_kernel<<<(E_EDGES * DD + 255) / 256, 256>>>(x, e_out, erow, ecol, t);
    combine_kernel<<<(N_NODES * DD + 255) / 256, 256>>>(x);
    dim3 g1((N_NODES + 127) / 128, 2);
    mlp1_kernel<<<g1, 256, smem_gemm>>>(W_m1, b_m1);
    bn_stats_kernel<<<(N_NODES + 63) / 64, 256>>>();
    bn_finalize_kernel<<<1, 256>>>(g_bn, b_bn);
    mlp2_kernel<<<(N_NODES + 127) / 128, 256, smem_gemm2>>>(W_m2, b_m2);
    node_out_kernel<<<N_NODES, 128>>>(x, scale, g_n, b_n, xout);
}

// round 5
// speedup vs baseline: 1.5830x; 1.2040x over previous
#include <cuda_runtime.h>
#include <cuda_bf16.h>
#include <math.h>
#include <stdint.h>

#define N_NODES 25000
#define E_EDGES 250000
#define DD 128

// ---------------- scratch (device globals; no allocation allowed) ----------
__device__ float2 g_dn[(size_t)N_NODES * DD];        // (denom, numerator)
__device__ float  g_xw[(size_t)N_NODES * 256];       // [xW1 | xW2] per node
__device__ float  g_h1[(size_t)N_NODES * 2 * DD];    // after first MLP linear
__device__ float  g_h[(size_t)N_NODES * DD];         // after second MLP linear
__device__ float  g_bnsum[2 * DD];
__device__ float  g_bnsq[2 * DD];
__device__ float  g_bnscale[2 * DD];
__device__ float  g_bnshift[2 * DD];
// W_e^T split to bf16 hi/lo, padded rows: [6 k-chunk images][128 n][72 k]
#define KP 72
#define SP (KP / 2)      // u32 row stride = 36 (conflict-free LDS)
__device__ unsigned short g_Bh[6 * 128 * KP];
__device__ unsigned short g_Bl[6 * 128 * KP];

// ---------------- init ------------------------------------------------------
__global__ void init_kernel() {
    int i = blockIdx.x * 256 + threadIdx.x;
    if (i < N_NODES * DD) g_dn[i] = make_float2(0.f, 0.f);
    if (i < 2 * DD) { g_bnsum[i] = 0.f; g_bnsq[i] = 0.f; }
}

// ---------------- prep: W_e -> transposed, split, padded --------------------
// image g = k>>6 holds B[n][kk] = W_e[g*64+kk][n]
__global__ void prep_B_kernel(const float* __restrict__ W_e) {
    int i = blockIdx.x * 256 + threadIdx.x;
    if (i >= 384 * 128) return;
    int k = i >> 7, n = i & 127;
    float v = W_e[i];
    __nv_bfloat16 h = __float2bfloat16(v);
    __nv_bfloat16 l = __float2bfloat16(v - __bfloat162float(h));
    int g = k >> 6, kk = k & 63;
    int idx = (g * 128 + n) * KP + kk;
    g_Bh[idx] = __bfloat16_as_ushort(h);
    g_Bl[idx] = __bfloat16_as_ushort(l);
}

// ---------------- shared HMMA machinery -------------------------------------
__device__ __forceinline__ void mma_bf16(float* d, const uint32_t* a,
                                         uint32_t b0, uint32_t b1) {
    asm volatile(
        "mma.sync.aligned.m16n8k16.row.col.f32.bf16.bf16.f32 "
        "{%0,%1,%2,%3}, {%4,%5,%6,%7}, {%8,%9}, {%0,%1,%2,%3};"
        : "+f"(d[0]), "+f"(d[1]), "+f"(d[2]), "+f"(d[3])
        : "r"(a[0]), "r"(a[1]), "r"(a[2]), "r"(a[3]), "r"(b0), "r"(b1));
}

// convert one 32-float strip (fp32 -> bf16 hi/lo packed) into padded smem
__device__ __forceinline__ void split_store_row(const float* src, uint32_t* Ahi,
                                                uint32_t* Alo, int base) {
#pragma unroll
    for (int i = 0; i < 8; ++i) {
        float4 v = ((const float4*)src)[i];
        __nv_bfloat16 h0 = __float2bfloat16(v.x), h1 = __float2bfloat16(v.y);
        __nv_bfloat16 h2 = __float2bfloat16(v.z), h3 = __float2bfloat16(v.w);
        __nv_bfloat16 l0 = __float2bfloat16(v.x - __bfloat162float(h0));
        __nv_bfloat16 l1 = __float2bfloat16(v.y - __bfloat162float(h1));
        __nv_bfloat16 l2 = __float2bfloat16(v.z - __bfloat162float(h2));
        __nv_bfloat16 l3 = __float2bfloat16(v.w - __bfloat162float(h3));
        Ahi[base + i * 2]     = (uint32_t)__bfloat16_as_ushort(h0) | ((uint32_t)__bfloat16_as_ushort(h1) << 16);
        Ahi[base + i * 2 + 1] = (uint32_t)__bfloat16_as_ushort(h2) | ((uint32_t)__bfloat16_as_ushort(h3) << 16);
        Alo[base + i * 2]     = (uint32_t)__bfloat16_as_ushort(l0) | ((uint32_t)__bfloat16_as_ushort(l1) << 16);
        Alo[base + i * 2 + 1] = (uint32_t)__bfloat16_as_ushort(l2) | ((uint32_t)__bfloat16_as_ushort(l3) << 16);
    }
}

// 3-term split-bf16 MMA over one 64-K chunk (per-warp 128x128 tile share)
__device__ __forceinline__ void mma_chunk(const uint32_t* Ahi, const uint32_t* Alo,
                                          const uint32_t* Bhi, const uint32_t* Blo,
                                          float acc[2][8][4], int wm, int wn, int lane) {
#pragma unroll
    for (int term = 0; term < 3; ++term) {
        const uint32_t* As = (term == 2) ? Alo : Ahi;
        const uint32_t* Bs = (term == 1) ? Blo : Bhi;
#pragma unroll
        for (int ks = 0; ks < 4; ++ks) {
            const int kb = ks * 8;
            uint32_t a[2][4];
#pragma unroll
            for (int mt = 0; mt < 2; ++mt) {
                int ar = wm * 32 + mt * 16 + (lane >> 2);
                int ac = kb + (lane & 3);
                a[mt][0] = As[ar * SP + ac];
                a[mt][1] = As[(ar + 8) * SP + ac];
                a[mt][2] = As[ar * SP + ac + 4];
                a[mt][3] = As[(ar + 8) * SP + ac + 4];
            }
#pragma unroll
            for (int nt = 0; nt < 8; ++nt) {
                int bn = wn * 64 + nt * 8 + (lane >> 2);
                uint32_t b0 = Bs[bn * SP + kb + (lane & 3)];
                uint32_t b1 = Bs[bn * SP + kb + (lane & 3) + 4];
                mma_bf16(acc[0][nt], a[0], b0, b1);
                mma_bf16(acc[1][nt], a[1], b0, b1);
            }
        }
    }
}

// smem layout (bytes) shared by node_pre / edge kernels
#define SM_IDX  0
#define SM_PAR  1024
#define SM_MUR  2560       // mu[128], rstd[128]
#define SM_AHI  4096
#define SM_ALO  (SM_AHI + 18432)
#define SM_BHI  (SM_ALO + 18432)
#define SM_BLO  (SM_BHI + 18432)
#define SM_ES   SM_AHI     // epilogue 128x129 float overlaps A/B
#define SM_TOTAL_TC (SM_BLO + 18432)

// ---------------- node precompute: g_xw = x @ [W_e[0:128] | W_e[128:256]] ---
__global__ __launch_bounds__(256, 2)
void node_pre_kernel(const float* __restrict__ x)
{
    extern __shared__ __align__(128) char smem[];
    const int tid = threadIdx.x, wid = tid >> 5, lane = tid & 31;
    const int r0 = blockIdx.x * 128;
    const int by = blockIdx.y;          // 0: xW1 (images 0,1), 1: xW2 (images 2,3)
    const int wm = wid >> 1, wn = wid & 1;

    uint32_t* Ahi = (uint32_t*)(smem + SM_AHI);
    uint32_t* Alo = (uint32_t*)(smem + SM_ALO);
    uint32_t* Bhi = (uint32_t*)(smem + SM_BHI);
    uint32_t* Blo = (uint32_t*)(smem + SM_BLO);

    float acc[2][8][4];
#pragma unroll
    for (int mt = 0; mt < 2; ++mt)
#pragma unroll
        for (int nt = 0; nt < 8; ++nt)
#pragma unroll
            for (int q = 0; q < 4; ++q) acc[mt][nt][q] = 0.f;

    for (int c = 0; c < 2; ++c) {
        if (c) __syncthreads();
        {
            int row = tid >> 1, half = tid & 1;
            int r = min(r0 + row, N_NODES - 1);
            const float* src = x + (size_t)r * 128 + c * 64 + half * 32;
            split_store_row(src, Ahi, Alo, row * SP + half * 16);
        }
        {
            int g = by * 2 + c;
            const uint32_t* sh = (const uint32_t*)g_Bh + g * (128 * SP);
            const uint32_t* sl = (const uint32_t*)g_Bl + g * (128 * SP);
#pragma unroll
            for (int j = tid; j < 128 * SP; j += 256) { Bhi[j] = sh[j]; Blo[j] = sl[j]; }
        }
        __syncthreads();
        mma_chunk(Ahi, Alo, Bhi, Blo, acc, wm, wn, lane);
    }
    // write fragments directly (float2 pairs)
#pragma unroll
    for (int mt = 0; mt < 2; ++mt) {
        int r = r0 + wm * 32 + mt * 16 + (lane >> 2);
#pragma unroll
        for (int nt = 0; nt < 8; ++nt) {
            int cc = by * 128 + wn * 64 + nt * 8 + ((lane & 3) << 1);
            if (r < N_NODES)
                *(float2*)&g_xw[(size_t)r * 256 + cc] = make_float2(acc[mt][nt][0], acc[mt][nt][1]);
            if (r + 8 < N_NODES)
                *(float2*)&g_xw[(size_t)(r + 8) * 256 + cc] = make_float2(acc[mt][nt][2], acc[mt][nt][3]);
        }
    }
}

// ---------------- edge kernel: edge_attr GEMM + LN + residual + fused agg ---
__global__ __launch_bounds__(256, 2)
void edge_mlp_tc(const float* __restrict__ x, const float* __restrict__ edge_attr,
                 const int* __restrict__ erow, const int* __restrict__ ecol,
                 const float* __restrict__ b_e, const float* __restrict__ g_e,
                 const float* __restrict__ be_e, const float* __restrict__ t_ptr,
                 float* __restrict__ e_out)
{
    extern __shared__ __align__(128) char smem[];
    const int tid = threadIdx.x, wid = tid >> 5, lane = tid & 31;
    const int e0 = blockIdx.x * 128;
    const int wm = wid >> 1, wn = wid & 1;

    int*   erow_s = (int*)(smem + SM_IDX);
    int*   ecol_s = erow_s + 128;
    float* par    = (float*)(smem + SM_PAR);
    float* mu_s   = (float*)(smem + SM_MUR);
    float* rs_s   = mu_s + 128;

    if (tid < 128) {
        int eid = min(e0 + tid, E_EDGES - 1);
        erow_s[tid] = erow[eid];
        ecol_s[tid] = ecol[eid];
        par[tid]       = b_e[tid];
        par[128 + tid] = g_e[tid];
        par[256 + tid] = be_e[tid];
    }
    __syncthreads();

    uint32_t* Ahi = (uint32_t*)(smem + SM_AHI);
    uint32_t* Alo = (uint32_t*)(smem + SM_ALO);
    uint32_t* Bhi = (uint32_t*)(smem + SM_BHI);
    uint32_t* Blo = (uint32_t*)(smem + SM_BLO);

    float acc[2][8][4];
#pragma unroll
    for (int mt = 0; mt < 2; ++mt)
#pragma unroll
        for (int nt = 0; nt < 8; ++nt)
#pragma unroll
            for (int q = 0; q < 4; ++q) acc[mt][nt][q] = 0.f;

    for (int c = 0; c < 2; ++c) {
        if (c) __syncthreads();
        {
            int row = tid >> 1, half = tid & 1;
            const float* src = edge_attr +
                (size_t)min(e0 + row, E_EDGES - 1) * 128 + c * 64 + half * 32;
            split_store_row(src, Ahi, Alo, row * SP + half * 16);
        }
        {
            int g = 4 + c;
            const uint32_t* sh = (const uint32_t*)g_Bh + g * (128 * SP);
            const uint32_t* sl = (const uint32_t*)g_Bl + g * (128 * SP);
#pragma unroll
            for (int j = tid; j < 128 * SP; j += 256) { Bhi[j] = sh[j]; Blo[j] = sl[j]; }
        }
        __syncthreads();
        mma_chunk(Ahi, Alo, Bhi, Blo, acc, wm, wn, lane);
    }
    __syncthreads();          // before reusing smem as Es

    float* Es = (float*)(smem + SM_ES);
#pragma unroll
    for (int mt = 0; mt < 2; ++mt) {
        int r = wm * 32 + mt * 16 + (lane >> 2);
#pragma unroll
        for (int nt = 0; nt < 8; ++nt) {
            int cc = wn * 64 + nt * 8 + ((lane & 3) << 1);
            Es[r * 129 + cc]           = acc[mt][nt][0];
            Es[r * 129 + cc + 1]       = acc[mt][nt][1];
            Es[(r + 8) * 129 + cc]     = acc[mt][nt][2];
            Es[(r + 8) * 129 + cc + 1] = acc[mt][nt][3];
        }
    }
    __syncthreads();

    // phase0: add node precomputes + bias, ReLU (coalesced gathered reads)
    for (int j = tid; j < 128 * 128; j += 256) {
        int el = j >> 7, cc = j & 127;
        if (e0 + el < E_EDGES) {
            float v = Es[el * 129 + cc] + par[cc]
                    + g_xw[(size_t)erow_s[el] * 256 + cc]
                    + g_xw[(size_t)ecol_s[el] * 256 + 128 + cc];
            Es[el * 129 + cc] = fmaxf(v, 0.f);
        }
    }
    __syncthreads();

    // phase1: per-edge LN stats
    if (tid < 128 && e0 + tid < E_EDGES) {
        const float* hrow = Es + tid * 129;
        float s = 0.f, ss = 0.f;
#pragma unroll 8
        for (int cc = 0; cc < 128; ++cc) { float v = hrow[cc]; s += v; ss += v * v; }
        float mu = s * (1.f / 128.f);
        mu_s[tid] = mu;
        rs_s[tid] = rsqrtf(ss * (1.f / 128.f) - mu * mu + 1e-5f);
    }
    __syncthreads();

    // phase2: normalize + residual -> e_out (coalesced), fused softmax-agg
    const float t = *t_ptr;
    for (int j = tid; j < 128 * 128; j += 256) {
        int el = j >> 7, cc = j & 127;
        int eid = e0 + el;
        if (eid < E_EDGES) {
            float v = Es[el * 129 + cc];
            float ln = (v - mu_s[el]) * rs_s[el] * par[128 + cc] + par[256 + cc];
            float e = ln + edge_attr[(size_t)eid * 128 + cc];
            e_out[(size_t)eid * 128 + cc] = e;
            float msg = fmaxf(x[(size_t)erow_s[el] * 128 + cc] + e, 0.f) + 1e-7f;
            float ex = __expf(msg * t);
            atomicAdd(&g_dn[(size_t)ecol_s[el] * 128 + cc], make_float2(ex, msg * ex));
        }
    }
}

// ---------------- node MLP linear 1 (fused combine): [N,128]@[128,256]+b ----
__global__ __launch_bounds__(256, 1)
void mlp1_kernel(const float* __restrict__ x,
                 const float* __restrict__ W_m1, const float* __restrict__ b_m1)
{
    extern __shared__ float sm[];
    float* As = sm;
    float* Bs = sm + 128 * 128;
    const int tid = threadIdx.x;
    const int r0 = blockIdx.x * 128;
    const int noff = blockIdx.y * 128;
    const int m0 = (tid >> 4) << 3;
    const int n0 = (tid & 15) << 3;
    float acc[8][8];
#pragma unroll
    for (int i = 0; i < 8; ++i)
#pragma unroll
        for (int j = 0; j < 8; ++j) acc[i][j] = 0.f;

#pragma unroll 4
    for (int j = tid; j < 128 * 32; j += 256) {
        int m = j >> 5, k4 = j & 31;
        int r = r0 + m; if (r >= N_NODES) r = N_NODES - 1;
        float4 xv = ((const float4*)x)[(size_t)r * 32 + k4];
        const float2* dnp = g_dn + (size_t)r * 128 + k4 * 4;
        float2 d0 = dnp[0], d1 = dnp[1], d2 = dnp[2], d3 = dnp[3];
        xv.x += (d0.x > 0.f) ? d0.y / d0.x : 0.f;
        xv.y += (d1.x > 0.f) ? d1.y / d1.x : 0.f;
        xv.z += (d2.x > 0.f) ? d2.y / d2.x : 0.f;
        xv.w += (d3.x > 0.f) ? d3.y / d3.x : 0.f;
        *((float4*)(As + m * 128 + k4 * 4)) = xv;
    }
#pragma unroll 4
    for (int j = tid; j < 128 * 32; j += 256) {
        int k = j >> 5, n4 = j & 31;
        *((float4*)(Bs + k * 128 + n4 * 4)) =
            ((const float4*)W_m1)[(size_t)k * 64 + (noff >> 2) + n4];
    }
    __syncthreads();
#pragma unroll 2
    for (int k = 0; k < 128; ++k) {
        float a[8];
#pragma unroll
        for (int i = 0; i < 8; ++i) a[i] = As[(m0 + i) * 128 + k];
        float4 bv0 = *(const float4*)(Bs + k * 128 + n0);
        float4 bv1 = *(const float4*)(Bs + k * 128 + n0 + 4);
        float b[8] = {bv0.x, bv0.y, bv0.z, bv0.w, bv1.x, bv1.y, bv1.z, bv1.w};
#pragma unroll
        for (int i = 0; i < 8; ++i)
#pragma unroll
            for (int j = 0; j < 8; ++j) acc[i][j] = fmaf(a[i], b[j], acc[i][j]);
    }
#pragma unroll
    for (int i = 0; i < 8; ++i) {
        int r = r0 + m0 + i;
        if (r < N_NODES) {
#pragma unroll
            for (int j = 0; j < 8; ++j)
                g_h1[(size_t)r * 256 + noff + n0 + j] = acc[i][j] + b_m1[noff + n0 + j];
        }
    }
}

// ---------------- BatchNorm stats (training-mode, biased var) ---------------
__global__ void bn_stats_kernel() {
    int c = threadIdx.x;
    int r0 = blockIdx.x * 64;
    int rend = min(r0 + 64, N_NODES);
    float s = 0.f, ss = 0.f;
    for (int r = r0; r < rend; ++r) {
        float v = g_h1[(size_t)r * 256 + c];
        s += v; ss += v * v;
    }
    atomicAdd(&g_bnsum[c], s);
    atomicAdd(&g_bnsq[c], ss);
}

__global__ void bn_finalize_kernel(const float* __restrict__ g_bn,
                                   const float* __restrict__ b_bn) {
    int c = threadIdx.x;
    float mean = g_bnsum[c] * (1.f / N_NODES);
    float var = g_bnsq[c] * (1.f / N_NODES) - mean * mean;
    float rstd = rsqrtf(var + 1e-5f);
    float a = rstd * g_bn[c];
    g_bnscale[c] = a;
    g_bnshift[c] = b_bn[c] - mean * a;
}

// ---------------- node MLP linear 2 with fused BN+ReLU on A-load ------------
__global__ __launch_bounds__(256, 1)
void mlp2_kernel(const float* __restrict__ W_m2, const float* __restrict__ b_m2)
{
    extern __shared__ float sm[];
    float* As = sm;
    float* Bs = sm + 128 * 128;
    float* sc = sm + 2 * 128 * 128;
    float* sh = sc + 256;
    const int tid = threadIdx.x;
    sc[tid] = g_bnscale[tid];
    sh[tid] = g_bnshift[tid];
    const int r0 = blockIdx.x * 128;
    const int m0 = (tid >> 4) << 3;
    const int n0 = (tid & 15) << 3;
    float acc[8][8];
#pragma unroll
    for (int i = 0; i < 8; ++i)
#pragma unroll
        for (int j = 0; j < 8; ++j) acc[i][j] = 0.f;
    __syncthreads();

    for (int cc = 0; cc < 2; ++cc) {
#pragma unroll 4
        for (int j = tid; j < 128 * 32; j += 256) {
            int m = j >> 5, k4 = j & 31;
            int r = r0 + m; if (r >= N_NODES) r = N_NODES - 1;
            float4 v = ((const float4*)g_h1)[(size_t)r * 64 + cc * 32 + k4];
            int kk = cc * 128 + k4 * 4;
            v.x = fmaxf(v.x * sc[kk]     + sh[kk],     0.f);
            v.y = fmaxf(v.y * sc[kk + 1] + sh[kk + 1], 0.f);
            v.z = fmaxf(v.z * sc[kk + 2] + sh[kk + 2], 0.f);
            v.w = fmaxf(v.w * sc[kk + 3] + sh[kk + 3], 0.f);
            *((float4*)(As + m * 128 + k4 * 4)) = v;
        }
#pragma unroll 4
        for (int j = tid; j < 128 * 32; j += 256) {
            int k = j >> 5, n4 = j & 31;
            *((float4*)(Bs + k * 128 + n4 * 4)) =
                ((const float4*)W_m2)[(size_t)(cc * 128 + k) * 32 + n4];
        }
        __syncthreads();
#pragma unroll 2
        for (int k = 0; k < 128; ++k) {
            float a[8];
#pragma unroll
            for (int i = 0; i < 8; ++i) a[i] = As[(m0 + i) * 128 + k];
            float4 bv0 = *(const float4*)(Bs + k * 128 + n0);
            float4 bv1 = *(const float4*)(Bs + k * 128 + n0 + 4);
            float b[8] = {bv0.x, bv0.y, bv0.z, bv0.w, bv1.x, bv1.y, bv1.z, bv1.w};
#pragma unroll
            for (int i = 0; i < 8; ++i)
#pragma unroll
                for (int j = 0; j < 8; ++j) acc[i][j] = fmaf(a[i], b[j], acc[i][j]);
        }
        __syncthreads();
    }
#pragma unroll
    for (int i = 0; i < 8; ++i) {
        int r = r0 + m0 + i;
        if (r < N_NODES) {
#pragma unroll
            for (int j = 0; j < 8; ++j)
                g_h[(size_t)r * 128 + n0 + j] = acc[i][j] + b_m2[n0 + j];
        }
    }
}

// ---------------- MessageNorm + residual + node LayerNorm -------------------
__device__ __forceinline__ float breduce(float v, float* sbuf) {
#pragma unroll
    for (int o = 16; o > 0; o >>= 1) v += __shfl_down_sync(0xffffffffu, v, o);
    if ((threadIdx.x & 31) == 0) sbuf[threadIdx.x >> 5] = v;
    __syncthreads();
    float r = sbuf[0] + sbuf[1] + sbuf[2] + sbuf[3];
    __syncthreads();
    return r;
}

__global__ __launch_bounds__(128)
void node_out_kernel(const float* __restrict__ x, const float* __restrict__ scale_ptr,
                     const float* __restrict__ g_n, const float* __restrict__ b_n,
                     float* __restrict__ xout)
{
    __shared__ float sbuf[4];
    int node = blockIdx.x;
    int c = threadIdx.x;
    float hv = g_h[(size_t)node * 128 + c];
    float xv = x[(size_t)node * 128 + c];
    float hn = sqrtf(breduce(hv * hv, sbuf));
    float xn = sqrtf(breduce(xv * xv, sbuf));
    float r = xv + hv / fmaxf(hn, 1e-12f) * xn * (*scale_ptr);
    float mu = breduce(r, sbuf) * (1.f / 128.f);
    float dv = r - mu;
    float var = breduce(dv * dv, sbuf) * (1.f / 128.f);
    xout[(size_t)node * 128 + c] = dv * rsqrtf(var + 1e-5f) * g_n[c] + b_n[c];
}

// ---------------- launch ----------------------------------------------------
extern "C" void kernel_launch(void* const* d_in, const int* in_sizes, int n_in,
                              void* d_out, int out_size)
{
    const float* x        = (const float*)d_in[0];
    const float* edge_attr= (const float*)d_in[1];
    const int*   eidx     = (const int*)  d_in[2];
    const float* W_e      = (const float*)d_in[3];
    const float* b_e      = (const float*)d_in[4];
    const float* g_e      = (const float*)d_in[5];
    const float* be_e     = (const float*)d_in[6];
    const float* t        = (const float*)d_in[7];
    const float* W_m1     = (const float*)d_in[8];
    const float* b_m1     = (const float*)d_in[9];
    const float* g_bn     = (const float*)d_in[10];
    const float* b_bn     = (const float*)d_in[11];
    const float* W_m2     = (const float*)d_in[12];
    const float* b_m2     = (const float*)d_in[13];
    const float* scale    = (const float*)d_in[14];
    const float* g_n      = (const float*)d_in[15];
    const float* b_n      = (const float*)d_in[16];
    const int* erow = eidx;
    const int* ecol = eidx + E_EDGES;
    float* xout  = (float*)d_out;
    float* e_out = (float*)d_out + (size_t)N_NODES * DD;

    const int smem_gemm  = 2 * 128 * 128 * 4;
    const int smem_gemm2 = (2 * 128 * 128 + 512) * 4;
    cudaFuncSetAttribute((const void*)node_pre_kernel,
                         cudaFuncAttributeMaxDynamicSharedMemorySize, SM_TOTAL_TC);
    cudaFuncSetAttribute((const void*)edge_mlp_tc,
                         cudaFuncAttributeMaxDynamicSharedMemorySize, SM_TOTAL_TC);
    cudaFuncSetAttribute((const void*)mlp1_kernel,
                         cudaFuncAttributeMaxDynamicSharedMemorySize, smem_gemm);
    cudaFuncSetAttribute((const void*)mlp2_kernel,
                         cudaFuncAttributeMaxDynamicSharedMemorySize, smem_gemm2);

    init_kernel<<<(N_NODES * DD + 255) / 256, 256>>>();
    prep_B_kernel<<<(384 * 128 + 255) / 256, 256>>>(W_e);
    dim3 gn((N_NODES + 127) / 128, 2);
    node_pre_kernel<<<gn, 256, SM_TOTAL_TC>>>(x);
    edge_mlp_tc<<<(E_EDGES + 127) / 128, 256, SM_TOTAL_TC>>>(
        x, edge_attr, erow, ecol, b_e, g_e, be_e, t, e_out);
    dim3 g1((N_NODES + 127) / 128, 2);
    mlp1_kernel<<<g1, 256, smem_gemm>>>(x, W_m1, b_m1);
    bn_stats_kernel<<<(N_NODES + 63) / 64, 256>>>();
    bn_finalize_kernel<<<1, 256>>>(g_bn, b_bn);
    mlp2_kernel<<<(N_NODES + 127) / 128, 256, smem_gemm2>>>(W_m2, b_m2);
    node_out_kernel<<<N_NODES, 128>>>(x, scale, g_n, b_n, xout);
}

// round 6
// speedup vs baseline: 1.8231x; 1.1517x over previous
#include <cuda_runtime.h>
#include <cuda_bf16.h>
#include <math.h>
#include <stdint.h>

#define N_NODES 25000
#define E_EDGES 250000
#define DD 128

// ---------------- scratch (device globals; no allocation allowed) ----------
__device__ float2 g_dn[(size_t)N_NODES * DD];        // (denom, numerator)
__device__ float  g_xw[(size_t)N_NODES * 256];       // [xW1 | xW2] per node
__device__ float  g_h1[(size_t)N_NODES * 2 * DD];    // after first MLP linear
__device__ float  g_h[(size_t)N_NODES * DD];         // after second MLP linear
__device__ float  g_bnsum[2 * DD];
__device__ float  g_bnsq[2 * DD];
__device__ float  g_bnscale[2 * DD];
__device__ float  g_bnshift[2 * DD];
// W_e^T split to bf16 hi/lo, padded rows: [6 k-chunk images][128 n][72 k]
#define KP 72
#define SP (KP / 2)      // u32 row stride = 36 (conflict-free LDS)
__device__ unsigned short g_Bh[6 * 128 * KP];
__device__ unsigned short g_Bl[6 * 128 * KP];

// ---------------- init ------------------------------------------------------
__global__ void init_kernel() {
    int i = blockIdx.x * 256 + threadIdx.x;
    if (i < N_NODES * DD) g_dn[i] = make_float2(0.f, 0.f);
    if (i < 2 * DD) { g_bnsum[i] = 0.f; g_bnsq[i] = 0.f; }
}

// ---------------- prep: W_e -> transposed, split, padded --------------------
__global__ void prep_B_kernel(const float* __restrict__ W_e) {
    int i = blockIdx.x * 256 + threadIdx.x;
    if (i >= 384 * 128) return;
    int k = i >> 7, n = i & 127;
    float v = W_e[i];
    __nv_bfloat16 h = __float2bfloat16(v);
    __nv_bfloat16 l = __float2bfloat16(v - __bfloat162float(h));
    int g = k >> 6, kk = k & 63;
    int idx = (g * 128 + n) * KP + kk;
    g_Bh[idx] = __bfloat16_as_ushort(h);
    g_Bl[idx] = __bfloat16_as_ushort(l);
}

// ---------------- shared HMMA machinery -------------------------------------
__device__ __forceinline__ void mma_bf16(float* d, const uint32_t* a,
                                         uint32_t b0, uint32_t b1) {
    asm volatile(
        "mma.sync.aligned.m16n8k16.row.col.f32.bf16.bf16.f32 "
        "{%0,%1,%2,%3}, {%4,%5,%6,%7}, {%8,%9}, {%0,%1,%2,%3};"
        : "+f"(d[0]), "+f"(d[1]), "+f"(d[2]), "+f"(d[3])
        : "r"(a[0]), "r"(a[1]), "r"(a[2]), "r"(a[3]), "r"(b0), "r"(b1));
}

__device__ __forceinline__ void red_v4(float* gp, float a, float b, float c, float d) {
    asm volatile("red.global.add.v4.f32 [%0], {%1,%2,%3,%4};"
                 :: "l"(gp), "f"(a), "f"(b), "f"(c), "f"(d) : "memory");
}

__device__ __forceinline__ void split_store_row(const float* src, uint32_t* Ahi,
                                                uint32_t* Alo, int base) {
#pragma unroll
    for (int i = 0; i < 8; ++i) {
        float4 v = ((const float4*)src)[i];
        __nv_bfloat16 h0 = __float2bfloat16(v.x), h1 = __float2bfloat16(v.y);
        __nv_bfloat16 h2 = __float2bfloat16(v.z), h3 = __float2bfloat16(v.w);
        __nv_bfloat16 l0 = __float2bfloat16(v.x - __bfloat162float(h0));
        __nv_bfloat16 l1 = __float2bfloat16(v.y - __bfloat162float(h1));
        __nv_bfloat16 l2 = __float2bfloat16(v.z - __bfloat162float(h2));
        __nv_bfloat16 l3 = __float2bfloat16(v.w - __bfloat162float(h3));
        Ahi[base + i * 2]     = (uint32_t)__bfloat16_as_ushort(h0) | ((uint32_t)__bfloat16_as_ushort(h1) << 16);
        Ahi[base + i * 2 + 1] = (uint32_t)__bfloat16_as_ushort(h2) | ((uint32_t)__bfloat16_as_ushort(h3) << 16);
        Alo[base + i * 2]     = (uint32_t)__bfloat16_as_ushort(l0) | ((uint32_t)__bfloat16_as_ushort(l1) << 16);
        Alo[base + i * 2 + 1] = (uint32_t)__bfloat16_as_ushort(l2) | ((uint32_t)__bfloat16_as_ushort(l3) << 16);
    }
}

__device__ __forceinline__ void mma_chunk(const uint32_t* Ahi, const uint32_t* Alo,
                                          const uint32_t* Bhi, const uint32_t* Blo,
                                          float acc[2][8][4], int wm, int wn, int lane) {
#pragma unroll
    for (int term = 0; term < 3; ++term) {
        const uint32_t* As = (term == 2) ? Alo : Ahi;
        const uint32_t* Bs = (term == 1) ? Blo : Bhi;
#pragma unroll
        for (int ks = 0; ks < 4; ++ks) {
            const int kb = ks * 8;
            uint32_t a[2][4];
#pragma unroll
            for (int mt = 0; mt < 2; ++mt) {
                int ar = wm * 32 + mt * 16 + (lane >> 2);
                int ac = kb + (lane & 3);
                a[mt][0] = As[ar * SP + ac];
                a[mt][1] = As[(ar + 8) * SP + ac];
                a[mt][2] = As[ar * SP + ac + 4];
                a[mt][3] = As[(ar + 8) * SP + ac + 4];
            }
#pragma unroll
            for (int nt = 0; nt < 8; ++nt) {
                int bn = wn * 64 + nt * 8 + (lane >> 2);
                uint32_t b0 = Bs[bn * SP + kb + (lane & 3)];
                uint32_t b1 = Bs[bn * SP + kb + (lane & 3) + 4];
                mma_bf16(acc[0][nt], a[0], b0, b1);
                mma_bf16(acc[1][nt], a[1], b0, b1);
            }
        }
    }
}

// smem layout (bytes)
#define SM_IDX  0
#define SM_PAR  1024
#define SM_MUR  2560       // mu[128], rstd[128]
#define SM_AHI  4096
#define SM_ALO  (SM_AHI + 18432)
#define SM_BHI  (SM_ALO + 18432)
#define SM_BLO  (SM_BHI + 18432)
#define SM_ES   SM_AHI     // epilogue 128 x 132 float (67584 B) overlaps A/B
#define ESW     132
#define ES4     33
#define SM_TOTAL_TC (SM_BLO + 18432)

// ---------------- node precompute: g_xw = x @ [W_e[0:128] | W_e[128:256]] ---
__global__ __launch_bounds__(256, 2)
void node_pre_kernel(const float* __restrict__ x)
{
    extern __shared__ __align__(128) char smem[];
    const int tid = threadIdx.x, wid = tid >> 5, lane = tid & 31;
    const int r0 = blockIdx.x * 128;
    const int by = blockIdx.y;
    const int wm = wid >> 1, wn = wid & 1;

    uint32_t* Ahi = (uint32_t*)(smem + SM_AHI);
    uint32_t* Alo = (uint32_t*)(smem + SM_ALO);
    uint32_t* Bhi = (uint32_t*)(smem + SM_BHI);
    uint32_t* Blo = (uint32_t*)(smem + SM_BLO);

    float acc[2][8][4];
#pragma unroll
    for (int mt = 0; mt < 2; ++mt)
#pragma unroll
        for (int nt = 0; nt < 8; ++nt)
#pragma unroll
            for (int q = 0; q < 4; ++q) acc[mt][nt][q] = 0.f;

    for (int c = 0; c < 2; ++c) {
        if (c) __syncthreads();
        {
            int row = tid >> 1, half = tid & 1;
            int r = min(r0 + row, N_NODES - 1);
            const float* src = x + (size_t)r * 128 + c * 64 + half * 32;
            split_store_row(src, Ahi, Alo, row * SP + half * 16);
        }
        {
            int g = by * 2 + c;
            const uint32_t* sh = (const uint32_t*)g_Bh + g * (128 * SP);
            const uint32_t* sl = (const uint32_t*)g_Bl + g * (128 * SP);
#pragma unroll
            for (int j = tid; j < 128 * SP; j += 256) { Bhi[j] = sh[j]; Blo[j] = sl[j]; }
        }
        __syncthreads();
        mma_chunk(Ahi, Alo, Bhi, Blo, acc, wm, wn, lane);
    }
#pragma unroll
    for (int mt = 0; mt < 2; ++mt) {
        int r = r0 + wm * 32 + mt * 16 + (lane >> 2);
#pragma unroll
        for (int nt = 0; nt < 8; ++nt) {
            int cc = by * 128 + wn * 64 + nt * 8 + ((lane & 3) << 1);
            if (r < N_NODES)
                *(float2*)&g_xw[(size_t)r * 256 + cc] = make_float2(acc[mt][nt][0], acc[mt][nt][1]);
            if (r + 8 < N_NODES)
                *(float2*)&g_xw[(size_t)(r + 8) * 256 + cc] = make_float2(acc[mt][nt][2], acc[mt][nt][3]);
        }
    }
}

// ---------------- edge kernel: GEMM + gathers + LN + residual + fused agg ---
__global__ __launch_bounds__(256, 2)
void edge_mlp_tc(const float* __restrict__ x, const float* __restrict__ edge_attr,
                 const int* __restrict__ erow, const int* __restrict__ ecol,
                 const float* __restrict__ b_e, const float* __restrict__ g_e,
                 const float* __restrict__ be_e, const float* __restrict__ t_ptr,
                 float* __restrict__ e_out)
{
    extern __shared__ __align__(128) char smem[];
    const int tid = threadIdx.x, wid = tid >> 5, lane = tid & 31;
    const int e0 = blockIdx.x * 128;
    const int wm = wid >> 1, wn = wid & 1;

    int*   erow_s = (int*)(smem + SM_IDX);
    int*   ecol_s = erow_s + 128;
    float* par    = (float*)(smem + SM_PAR);
    float* mu_s   = (float*)(smem + SM_MUR);
    float* rs_s   = mu_s + 128;

    if (tid < 128) {
        int eid = min(e0 + tid, E_EDGES - 1);
        erow_s[tid] = erow[eid];
        ecol_s[tid] = ecol[eid];
        par[tid]       = b_e[tid];
        par[128 + tid] = g_e[tid];
        par[256 + tid] = be_e[tid];
    }
    __syncthreads();

    uint32_t* Ahi = (uint32_t*)(smem + SM_AHI);
    uint32_t* Alo = (uint32_t*)(smem + SM_ALO);
    uint32_t* Bhi = (uint32_t*)(smem + SM_BHI);
    uint32_t* Blo = (uint32_t*)(smem + SM_BLO);

    float acc[2][8][4];
#pragma unroll
    for (int mt = 0; mt < 2; ++mt)
#pragma unroll
        for (int nt = 0; nt < 8; ++nt)
#pragma unroll
            for (int q = 0; q < 4; ++q) acc[mt][nt][q] = 0.f;

    for (int c = 0; c < 2; ++c) {
        if (c) __syncthreads();
        {
            int row = tid >> 1, half = tid & 1;
            const float* src = edge_attr +
                (size_t)min(e0 + row, E_EDGES - 1) * 128 + c * 64 + half * 32;
            split_store_row(src, Ahi, Alo, row * SP + half * 16);
        }
        {
            int g = 4 + c;
            const uint32_t* sh = (const uint32_t*)g_Bh + g * (128 * SP);
            const uint32_t* sl = (const uint32_t*)g_Bl + g * (128 * SP);
#pragma unroll
            for (int j = tid; j < 128 * SP; j += 256) { Bhi[j] = sh[j]; Blo[j] = sl[j]; }
        }
        __syncthreads();
        mma_chunk(Ahi, Alo, Bhi, Blo, acc, wm, wn, lane);
    }
    __syncthreads();          // smem -> Es reuse

    float* Es = (float*)(smem + SM_ES);
#pragma unroll
    for (int mt = 0; mt < 2; ++mt) {
        int r = wm * 32 + mt * 16 + (lane >> 2);
#pragma unroll
        for (int nt = 0; nt < 8; ++nt) {
            int cc = wn * 64 + nt * 8 + ((lane & 3) << 1);
            Es[r * ESW + cc]           = acc[mt][nt][0];
            Es[r * ESW + cc + 1]       = acc[mt][nt][1];
            Es[(r + 8) * ESW + cc]     = acc[mt][nt][2];
            Es[(r + 8) * ESW + cc + 1] = acc[mt][nt][3];
        }
    }
    __syncthreads();

    // Phase A: add node precomputes + bias, ReLU, LN stats (2 threads/edge,
    // pair covers contiguous 32B of the gathered rows -> full sectors)
    {
        int el = tid >> 1, h = tid & 1;
        float4* Es4 = (float4*)Es;
        const float4* par4 = (const float4*)par;
        const float4* xr4 = (const float4*)(g_xw + (size_t)erow_s[el] * 256);
        const float4* xc4 = (const float4*)(g_xw + (size_t)ecol_s[el] * 256 + 128);
        float s = 0.f, ss = 0.f;
#pragma unroll
        for (int i = 0; i < 16; ++i) {
            int q = i * 2 + h;            // float4 index within 128 ch
            float4 es = Es4[el * ES4 + q];
            float4 bb = par4[q];
            float4 xr = xr4[q];
            float4 xc = xc4[q];
            float4 v;
            v.x = fmaxf(es.x + bb.x + xr.x + xc.x, 0.f);
            v.y = fmaxf(es.y + bb.y + xr.y + xc.y, 0.f);
            v.z = fmaxf(es.z + bb.z + xr.z + xc.z, 0.f);
            v.w = fmaxf(es.w + bb.w + xr.w + xc.w, 0.f);
            Es4[el * ES4 + q] = v;
            s += v.x + v.y + v.z + v.w;
            ss += v.x * v.x + v.y * v.y + v.z * v.z + v.w * v.w;
        }
        s  += __shfl_xor_sync(0xffffffffu, s, 1);
        ss += __shfl_xor_sync(0xffffffffu, ss, 1);
        float mu = s * (1.f / 128.f);
        mu_s[el] = mu;
        rs_s[el] = rsqrtf(ss * (1.f / 128.f) - mu * mu + 1e-5f);
    }
    __syncthreads();

    // Phase B: normalize + residual -> e_out, fused softmax-agg (v4 RED)
    const float t = *t_ptr;
    const float4* par4 = (const float4*)par;
#pragma unroll
    for (int j = tid; j < 128 * 32; j += 256) {
        int el = j >> 5, q = j & 31;
        int eid = e0 + el;
        if (eid < E_EDGES) {
            float4 es = ((float4*)Es)[el * ES4 + q];
            float mu = mu_s[el], rs = rs_s[el];
            float4 g = par4[32 + q], b = par4[64 + q];
            float4 ea = ((const float4*)edge_attr)[(size_t)eid * 32 + q];
            float4 e;
            e.x = (es.x - mu) * rs * g.x + b.x + ea.x;
            e.y = (es.y - mu) * rs * g.y + b.y + ea.y;
            e.z = (es.z - mu) * rs * g.z + b.z + ea.z;
            e.w = (es.w - mu) * rs * g.w + b.w + ea.w;
            ((float4*)e_out)[(size_t)eid * 32 + q] = e;
            float4 xv = ((const float4*)x)[(size_t)erow_s[el] * 32 + q];
            float m0 = fmaxf(xv.x + e.x, 0.f) + 1e-7f;
            float m1 = fmaxf(xv.y + e.y, 0.f) + 1e-7f;
            float m2 = fmaxf(xv.z + e.z, 0.f) + 1e-7f;
            float m3 = fmaxf(xv.w + e.w, 0.f) + 1e-7f;
            float x0 = __expf(m0 * t), x1 = __expf(m1 * t);
            float x2 = __expf(m2 * t), x3 = __expf(m3 * t);
            float* base = (float*)(g_dn + (size_t)ecol_s[el] * 128 + q * 4);
            red_v4(base,     x0, m0 * x0, x1, m1 * x1);
            red_v4(base + 4, x2, m2 * x2, x3, m3 * x3);
        }
    }
}

// ---------------- node MLP linear 1 (fused combine + BN stats) --------------
__global__ __launch_bounds__(256, 1)
void mlp1_kernel(const float* __restrict__ x,
                 const float* __restrict__ W_m1, const float* __restrict__ b_m1)
{
    extern __shared__ float sm[];
    float* As = sm;
    float* Bs = sm + 128 * 128;
    const int tid = threadIdx.x;
    const int r0 = blockIdx.x * 128;
    const int noff = blockIdx.y * 128;
    const int m0 = (tid >> 4) << 3;
    const int n0 = (tid & 15) << 3;
    float acc[8][8];
#pragma unroll
    for (int i = 0; i < 8; ++i)
#pragma unroll
        for (int j = 0; j < 8; ++j) acc[i][j] = 0.f;

#pragma unroll 4
    for (int j = tid; j < 128 * 32; j += 256) {
        int m = j >> 5, k4 = j & 31;
        int r = r0 + m; if (r >= N_NODES) r = N_NODES - 1;
        float4 xv = ((const float4*)x)[(size_t)r * 32 + k4];
        const float2* dnp = g_dn + (size_t)r * 128 + k4 * 4;
        float2 d0 = dnp[0], d1 = dnp[1], d2 = dnp[2], d3 = dnp[3];
        xv.x += (d0.x > 0.f) ? d0.y / d0.x : 0.f;
        xv.y += (d1.x > 0.f) ? d1.y / d1.x : 0.f;
        xv.z += (d2.x > 0.f) ? d2.y / d2.x : 0.f;
        xv.w += (d3.x > 0.f) ? d3.y / d3.x : 0.f;
        *((float4*)(As + m * 128 + k4 * 4)) = xv;
    }
#pragma unroll 4
    for (int j = tid; j < 128 * 32; j += 256) {
        int k = j >> 5, n4 = j & 31;
        *((float4*)(Bs + k * 128 + n4 * 4)) =
            ((const float4*)W_m1)[(size_t)k * 64 + (noff >> 2) + n4];
    }
    __syncthreads();
#pragma unroll 2
    for (int k = 0; k < 128; ++k) {
        float a[8];
#pragma unroll
        for (int i = 0; i < 8; ++i) a[i] = As[(m0 + i) * 128 + k];
        float4 bv0 = *(const float4*)(Bs + k * 128 + n0);
        float4 bv1 = *(const float4*)(Bs + k * 128 + n0 + 4);
        float b[8] = {bv0.x, bv0.y, bv0.z, bv0.w, bv1.x, bv1.y, bv1.z, bv1.w};
#pragma unroll
        for (int i = 0; i < 8; ++i)
#pragma unroll
            for (int j = 0; j < 8; ++j) acc[i][j] = fmaf(a[i], b[j], acc[i][j]);
    }
    // add bias, write out, and accumulate BN stats (valid rows only)
#pragma unroll
    for (int i = 0; i < 8; ++i) {
        int r = r0 + m0 + i;
        if (r < N_NODES) {
#pragma unroll
            for (int j = 0; j < 8; ++j) {
                acc[i][j] += b_m1[noff + n0 + j];
                g_h1[(size_t)r * 256 + noff + n0 + j] = acc[i][j];
            }
        }
    }
#pragma unroll
    for (int j = 0; j < 8; ++j) {
        float s = 0.f, ss = 0.f;
#pragma unroll
        for (int i = 0; i < 8; ++i) {
            if (r0 + m0 + i < N_NODES) { s += acc[i][j]; ss += acc[i][j] * acc[i][j]; }
        }
        atomicAdd(&g_bnsum[noff + n0 + j], s);
        atomicAdd(&g_bnsq[noff + n0 + j], ss);
    }
}

__global__ void bn_finalize_kernel(const float* __restrict__ g_bn,
                                   const float* __restrict__ b_bn) {
    int c = threadIdx.x;
    float mean = g_bnsum[c] * (1.f / N_NODES);
    float var = g_bnsq[c] * (1.f / N_NODES) - mean * mean;
    float rstd = rsqrtf(var + 1e-5f);
    float a = rstd * g_bn[c];
    g_bnscale[c] = a;
    g_bnshift[c] = b_bn[c] - mean * a;
}

// ---------------- node MLP linear 2 with fused BN+ReLU on A-load ------------
__global__ __launch_bounds__(256, 1)
void mlp2_kernel(const float* __restrict__ W_m2, const float* __restrict__ b_m2)
{
    extern __shared__ float sm[];
    float* As = sm;
    float* Bs = sm + 128 * 128;
    float* sc = sm + 2 * 128 * 128;
    float* sh = sc + 256;
    const int tid = threadIdx.x;
    sc[tid] = g_bnscale[tid];
    sh[tid] = g_bnshift[tid];
    const int r0 = blockIdx.x * 128;
    const int m0 = (tid >> 4) << 3;
    const int n0 = (tid & 15) << 3;
    float acc[8][8];
#pragma unroll
    for (int i = 0; i < 8; ++i)
#pragma unroll
        for (int j = 0; j < 8; ++j) acc[i][j] = 0.f;
    __syncthreads();

    for (int cc = 0; cc < 2; ++cc) {
#pragma unroll 4
        for (int j = tid; j < 128 * 32; j += 256) {
            int m = j >> 5, k4 = j & 31;
            int r = r0 + m; if (r >= N_NODES) r = N_NODES - 1;
            float4 v = ((const float4*)g_h1)[(size_t)r * 64 + cc * 32 + k4];
            int kk = cc * 128 + k4 * 4;
            v.x = fmaxf(v.x * sc[kk]     + sh[kk],     0.f);
            v.y = fmaxf(v.y * sc[kk + 1] + sh[kk + 1], 0.f);
            v.z = fmaxf(v.z * sc[kk + 2] + sh[kk + 2], 0.f);
            v.w = fmaxf(v.w * sc[kk + 3] + sh[kk + 3], 0.f);
            *((float4*)(As + m * 128 + k4 * 4)) = v;
        }
#pragma unroll 4
        for (int j = tid; j < 128 * 32; j += 256) {
            int k = j >> 5, n4 = j & 31;
            *((float4*)(Bs + k * 128 + n4 * 4)) =
                ((const float4*)W_m2)[(size_t)(cc * 128 + k) * 32 + n4];
        }
        __syncthreads();
#pragma unroll 2
        for (int k = 0; k < 128; ++k) {
            float a[8];
#pragma unroll
            for (int i = 0; i < 8; ++i) a[i] = As[(m0 + i) * 128 + k];
            float4 bv0 = *(const float4*)(Bs + k * 128 + n0);
            float4 bv1 = *(const float4*)(Bs + k * 128 + n0 + 4);
            float b[8] = {bv0.x, bv0.y, bv0.z, bv0.w, bv1.x, bv1.y, bv1.z, bv1.w};
#pragma unroll
            for (int i = 0; i < 8; ++i)
#pragma unroll
                for (int j = 0; j < 8; ++j) acc[i][j] = fmaf(a[i], b[j], acc[i][j]);
        }
        __syncthreads();
    }
#pragma unroll
    for (int i = 0; i < 8; ++i) {
        int r = r0 + m0 + i;
        if (r < N_NODES) {
#pragma unroll
            for (int j = 0; j < 8; ++j)
                g_h[(size_t)r * 128 + n0 + j] = acc[i][j] + b_m2[n0 + j];
        }
    }
}

// ---------------- MessageNorm + residual + node LayerNorm -------------------
__device__ __forceinline__ float breduce(float v, float* sbuf) {
#pragma unroll
    for (int o = 16; o > 0; o >>= 1) v += __shfl_down_sync(0xffffffffu, v, o);
    if ((threadIdx.x & 31) == 0) sbuf[threadIdx.x >> 5] = v;
    __syncthreads();
    float r = sbuf[0] + sbuf[1] + sbuf[2] + sbuf[3];
    __syncthreads();
    return r;
}

__global__ __launch_bounds__(128)
void node_out_kernel(const float* __restrict__ x, const float* __restrict__ scale_ptr,
                     const float* __restrict__ g_n, const float* __restrict__ b_n,
                     float* __restrict__ xout)
{
    __shared__ float sbuf[4];
    int node = blockIdx.x;
    int c = threadIdx.x;
    float hv = g_h[(size_t)node * 128 + c];
    float xv = x[(size_t)node * 128 + c];
    float hn = sqrtf(breduce(hv * hv, sbuf));
    float xn = sqrtf(breduce(xv * xv, sbuf));
    float r = xv + hv / fmaxf(hn, 1e-12f) * xn * (*scale_ptr);
    float mu = breduce(r, sbuf) * (1.f / 128.f);
    float dv = r - mu;
    float var = breduce(dv * dv, sbuf) * (1.f / 128.f);
    xout[(size_t)node * 128 + c] = dv * rsqrtf(var + 1e-5f) * g_n[c] + b_n[c];
}

// ---------------- launch ----------------------------------------------------
extern "C" void kernel_launch(void* const* d_in, const int* in_sizes, int n_in,
                              void* d_out, int out_size)
{
    const float* x        = (const float*)d_in[0];
    const float* edge_attr= (const float*)d_in[1];
    const int*   eidx     = (const int*)  d_in[2];
    const float* W_e      = (const float*)d_in[3];
    const float* b_e      = (const float*)d_in[4];
    const float* g_e      = (const float*)d_in[5];
    const float* be_e     = (const float*)d_in[6];
    const float* t        = (const float*)d_in[7];
    const float* W_m1     = (const float*)d_in[8];
    const float* b_m1     = (const float*)d_in[9];
    const float* g_bn     = (const float*)d_in[10];
    const float* b_bn     = (const float*)d_in[11];
    const float* W_m2     = (const float*)d_in[12];
    const float* b_m2     = (const float*)d_in[13];
    const float* scale    = (const float*)d_in[14];
    const float* g_n      = (const float*)d_in[15];
    const float* b_n      = (const float*)d_in[16];
    const int* erow = eidx;
    const int* ecol = eidx + E_EDGES;
    float* xout  = (float*)d_out;
    float* e_out = (float*)d_out + (size_t)N_NODES * DD;

    const int smem_gemm  = 2 * 128 * 128 * 4;
    const int smem_gemm2 = (2 * 128 * 128 + 512) * 4;
    cudaFuncSetAttribute((const void*)node_pre_kernel,
                         cudaFuncAttributeMaxDynamicSharedMemorySize, SM_TOTAL_TC);
    cudaFuncSetAttribute((const void*)edge_mlp_tc,
                         cudaFuncAttributeMaxDynamicSharedMemorySize, SM_TOTAL_TC);
    cudaFuncSetAttribute((const void*)mlp1_kernel,
                         cudaFuncAttributeMaxDynamicSharedMemorySize, smem_gemm);
    cudaFuncSetAttribute((const void*)mlp2_kernel,
                         cudaFuncAttributeMaxDynamicSharedMemorySize, smem_gemm2);

    init_kernel<<<(N_NODES * DD + 255) / 256, 256>>>();
    prep_B_kernel<<<(384 * 128 + 255) / 256, 256>>>(W_e);
    dim3 gn((N_NODES + 127) / 128, 2);
    node_pre_kernel<<<gn, 256, SM_TOTAL_TC>>>(x);
    edge_mlp_tc<<<(E_EDGES + 127) / 128, 256, SM_TOTAL_TC>>>(
        x, edge_attr, erow, ecol, b_e, g_e, be_e, t, e_out);
    dim3 g1((N_NODES + 127) / 128, 2);
    mlp1_kernel<<<g1, 256, smem_gemm>>>(x, W_m1, b_m1);
    bn_finalize_kernel<<<1, 256>>>(g_bn, b_bn);
    mlp2_kernel<<<(N_NODES + 127) / 128, 256, smem_gemm2>>>(W_m2, b_m2);
    node_out_kernel<<<N_NODES, 128>>>(x, scale, g_n, b_n, xout);
}

// round 7
// speedup vs baseline: 3.0838x; 1.6915x over previous
#include <cuda_runtime.h>
#include <cuda_bf16.h>
#include <math.h>
#include <stdint.h>

#define N_NODES 25000
#define E_EDGES 250000
#define DD 128

// ---------------- scratch ----------------------------------------------------
__device__ float2 g_dn[(size_t)N_NODES * DD];        // (denom, numerator)
__device__ float  g_xw[(size_t)N_NODES * 256];       // [xW1 | xW2] per node
__device__ float  g_h1[(size_t)N_NODES * 2 * DD];    // after first MLP linear
__device__ float2 g_bnstat[2 * DD];                  // (sum, sumsq)
__device__ float  g_bnscale[2 * DD];
__device__ float  g_bnshift[2 * DD];
// bf16 hi/lo weight images, padded rows [n][KP]
#define KP 72
#define SP (KP / 2)      // u32 row stride = 36 (conflict-free LDS)
__device__ unsigned short g_Bh[6 * 128 * KP];        // W_e^T, 6 images
__device__ unsigned short g_Bl[6 * 128 * KP];
__device__ unsigned short g_B1h[4 * 128 * KP];       // W_m1^T, 4 images
__device__ unsigned short g_B1l[4 * 128 * KP];
__device__ unsigned short g_B2h[4 * 128 * KP];       // W_m2^T, 4 images
__device__ unsigned short g_B2l[4 * 128 * KP];

// ---------------- init --------------------------------------------------------
__global__ void init_kernel() {
    int i = blockIdx.x * 256 + threadIdx.x;
    if (i < N_NODES * DD) g_dn[i] = make_float2(0.f, 0.f);
    if (i < 2 * DD) g_bnstat[i] = make_float2(0.f, 0.f);
}

// ---------------- prep: all weights -> transposed split padded images --------
__global__ void prep_kernel(const float* __restrict__ W_e,
                            const float* __restrict__ W_m1,
                            const float* __restrict__ W_m2) {
    int i = blockIdx.x * 256 + threadIdx.x;
    float v; int idx; unsigned short *dh, *dl;
    if (i < 384 * 128) {
        int k = i >> 7, n = i & 127;
        v = W_e[i];
        idx = (((k >> 6) * 128) + n) * KP + (k & 63);
        dh = g_Bh; dl = g_Bl;
    } else if (i < 384 * 128 + 128 * 256) {
        int j = i - 384 * 128;
        int k = j >> 8, n = j & 255;
        v = W_m1[j];
        int g = ((n >> 7) << 1) + (k >> 6);
        idx = (g * 128 + (n & 127)) * KP + (k & 63);
        dh = g_B1h; dl = g_B1l;
    } else if (i < 384 * 128 + 128 * 256 + 256 * 128) {
        int j = i - (384 * 128 + 128 * 256);
        int k = j >> 7, n = j & 127;
        v = W_m2[j];
        idx = (((k >> 6) * 128) + n) * KP + (k & 63);
        dh = g_B2h; dl = g_B2l;
    } else return;
    __nv_bfloat16 h = __float2bfloat16(v);
    __nv_bfloat16 l = __float2bfloat16(v - __bfloat162float(h));
    dh[idx] = __bfloat16_as_ushort(h);
    dl[idx] = __bfloat16_as_ushort(l);
}

// ---------------- HMMA machinery ---------------------------------------------
__device__ __forceinline__ void mma_bf16(float* d, const uint32_t* a,
                                         uint32_t b0, uint32_t b1) {
    asm volatile(
        "mma.sync.aligned.m16n8k16.row.col.f32.bf16.bf16.f32 "
        "{%0,%1,%2,%3}, {%4,%5,%6,%7}, {%8,%9}, {%0,%1,%2,%3};"
        : "+f"(d[0]), "+f"(d[1]), "+f"(d[2]), "+f"(d[3])
        : "r"(a[0]), "r"(a[1]), "r"(a[2]), "r"(a[3]), "r"(b0), "r"(b1));
}

__device__ __forceinline__ void red_v4(float* gp, float a, float b, float c, float d) {
    asm volatile("red.global.add.v4.f32 [%0], {%1,%2,%3,%4};"
                 :: "l"(gp), "f"(a), "f"(b), "f"(c), "f"(d) : "memory");
}

__device__ __forceinline__ void split4(float4 v, uint32_t& h0, uint32_t& h1,
                                       uint32_t& l0, uint32_t& l1) {
    __nv_bfloat16 a0 = __float2bfloat16(v.x), a1 = __float2bfloat16(v.y);
    __nv_bfloat16 a2 = __float2bfloat16(v.z), a3 = __float2bfloat16(v.w);
    __nv_bfloat16 b0 = __float2bfloat16(v.x - __bfloat162float(a0));
    __nv_bfloat16 b1 = __float2bfloat16(v.y - __bfloat162float(a1));
    __nv_bfloat16 b2 = __float2bfloat16(v.z - __bfloat162float(a2));
    __nv_bfloat16 b3 = __float2bfloat16(v.w - __bfloat162float(a3));
    h0 = (uint32_t)__bfloat16_as_ushort(a0) | ((uint32_t)__bfloat16_as_ushort(a1) << 16);
    h1 = (uint32_t)__bfloat16_as_ushort(a2) | ((uint32_t)__bfloat16_as_ushort(a3) << 16);
    l0 = (uint32_t)__bfloat16_as_ushort(b0) | ((uint32_t)__bfloat16_as_ushort(b1) << 16);
    l1 = (uint32_t)__bfloat16_as_ushort(b2) | ((uint32_t)__bfloat16_as_ushort(b3) << 16);
}

__device__ __forceinline__ void mma_chunk(const uint32_t* Ahi, const uint32_t* Alo,
                                          const uint32_t* Bhi, const uint32_t* Blo,
                                          float acc[2][8][4], int wm, int wn, int lane) {
#pragma unroll
    for (int term = 0; term < 3; ++term) {
        const uint32_t* As = (term == 2) ? Alo : Ahi;
        const uint32_t* Bs = (term == 1) ? Blo : Bhi;
#pragma unroll
        for (int ks = 0; ks < 4; ++ks) {
            const int kb = ks * 8;
            uint32_t a[2][4];
#pragma unroll
            for (int mt = 0; mt < 2; ++mt) {
                int ar = wm * 32 + mt * 16 + (lane >> 2);
                int ac = kb + (lane & 3);
                a[mt][0] = As[ar * SP + ac];
                a[mt][1] = As[(ar + 8) * SP + ac];
                a[mt][2] = As[ar * SP + ac + 4];
                a[mt][3] = As[(ar + 8) * SP + ac + 4];
            }
#pragma unroll
            for (int nt = 0; nt < 8; ++nt) {
                int bn = wn * 64 + nt * 8 + (lane >> 2);
                uint32_t b0 = Bs[bn * SP + kb + (lane & 3)];
                uint32_t b1 = Bs[bn * SP + kb + (lane & 3) + 4];
                mma_bf16(acc[0][nt], a[0], b0, b1);
                mma_bf16(acc[1][nt], a[1], b0, b1);
            }
        }
    }
}

// smem layout (bytes)
#define SM_IDX  0
#define SM_PAR  1024
#define SM_MUR  2560
#define SM_AHI  4096
#define SM_ALO  (SM_AHI + 18432)
#define SM_BHI  (SM_ALO + 18432)
#define SM_BLO  (SM_BHI + 18432)
#define SM_ES   SM_AHI
#define ESW     132
#define ES4     33
#define SM_TOTAL_TC (SM_BLO + 18432)          // 77824
#define SM_EXTRA    SM_TOTAL_TC               // mlp2 params: 1284 floats
#define SM2_TOTAL   (SM_EXTRA + 5200)

// ---------------- node precompute: g_xw = x @ [W_e 0:128 | 128:256] ----------
__global__ __launch_bounds__(256, 2)
void node_pre_kernel(const float* __restrict__ x)
{
    extern __shared__ __align__(128) char smem[];
    const int tid = threadIdx.x, wid = tid >> 5, lane = tid & 31;
    const int r0 = blockIdx.x * 128;
    const int by = blockIdx.y;
    const int wm = wid >> 1, wn = wid & 1;

    uint32_t* Ahi = (uint32_t*)(smem + SM_AHI);
    uint32_t* Alo = (uint32_t*)(smem + SM_ALO);
    uint32_t* Bhi = (uint32_t*)(smem + SM_BHI);
    uint32_t* Blo = (uint32_t*)(smem + SM_BLO);

    float acc[2][8][4];
#pragma unroll
    for (int mt = 0; mt < 2; ++mt)
#pragma unroll
        for (int nt = 0; nt < 8; ++nt)
#pragma unroll
            for (int q = 0; q < 4; ++q) acc[mt][nt][q] = 0.f;

    for (int c = 0; c < 2; ++c) {
        if (c) __syncthreads();
        {
            int row = tid >> 1, half = tid & 1;
            int r = min(r0 + row, N_NODES - 1);
            const float4* src = (const float4*)(x + (size_t)r * 128 + c * 64 + half * 32);
            int base = row * SP + half * 16;
#pragma unroll
            for (int i = 0; i < 8; ++i) {
                uint32_t h0, h1, l0, l1;
                split4(src[i], h0, h1, l0, l1);
                Ahi[base + i * 2] = h0; Ahi[base + i * 2 + 1] = h1;
                Alo[base + i * 2] = l0; Alo[base + i * 2 + 1] = l1;
            }
        }
        {
            int g = by * 2 + c;
            const uint32_t* sh = (const uint32_t*)g_Bh + g * (128 * SP);
            const uint32_t* sl = (const uint32_t*)g_Bl + g * (128 * SP);
#pragma unroll
            for (int j = tid; j < 128 * SP; j += 256) { Bhi[j] = sh[j]; Blo[j] = sl[j]; }
        }
        __syncthreads();
        mma_chunk(Ahi, Alo, Bhi, Blo, acc, wm, wn, lane);
    }
#pragma unroll
    for (int mt = 0; mt < 2; ++mt) {
        int r = r0 + wm * 32 + mt * 16 + (lane >> 2);
#pragma unroll
        for (int nt = 0; nt < 8; ++nt) {
            int cc = by * 128 + wn * 64 + nt * 8 + ((lane & 3) << 1);
            if (r < N_NODES)
                *(float2*)&g_xw[(size_t)r * 256 + cc] = make_float2(acc[mt][nt][0], acc[mt][nt][1]);
            if (r + 8 < N_NODES)
                *(float2*)&g_xw[(size_t)(r + 8) * 256 + cc] = make_float2(acc[mt][nt][2], acc[mt][nt][3]);
        }
    }
}

// ---------------- edge kernel (unchanged from R6) ----------------------------
__global__ __launch_bounds__(256, 2)
void edge_mlp_tc(const float* __restrict__ x, const float* __restrict__ edge_attr,
                 const int* __restrict__ erow, const int* __restrict__ ecol,
                 const float* __restrict__ b_e, const float* __restrict__ g_e,
                 const float* __restrict__ be_e, const float* __restrict__ t_ptr,
                 float* __restrict__ e_out)
{
    extern __shared__ __align__(128) char smem[];
    const int tid = threadIdx.x, wid = tid >> 5, lane = tid & 31;
    const int e0 = blockIdx.x * 128;
    const int wm = wid >> 1, wn = wid & 1;

    int*   erow_s = (int*)(smem + SM_IDX);
    int*   ecol_s = erow_s + 128;
    float* par    = (float*)(smem + SM_PAR);
    float* mu_s   = (float*)(smem + SM_MUR);
    float* rs_s   = mu_s + 128;

    if (tid < 128) {
        int eid = min(e0 + tid, E_EDGES - 1);
        erow_s[tid] = erow[eid];
        ecol_s[tid] = ecol[eid];
        par[tid]       = b_e[tid];
        par[128 + tid] = g_e[tid];
        par[256 + tid] = be_e[tid];
    }
    __syncthreads();

    uint32_t* Ahi = (uint32_t*)(smem + SM_AHI);
    uint32_t* Alo = (uint32_t*)(smem + SM_ALO);
    uint32_t* Bhi = (uint32_t*)(smem + SM_BHI);
    uint32_t* Blo = (uint32_t*)(smem + SM_BLO);

    float acc[2][8][4];
#pragma unroll
    for (int mt = 0; mt < 2; ++mt)
#pragma unroll
        for (int nt = 0; nt < 8; ++nt)
#pragma unroll
            for (int q = 0; q < 4; ++q) acc[mt][nt][q] = 0.f;

    for (int c = 0; c < 2; ++c) {
        if (c) __syncthreads();
        {
            int row = tid >> 1, half = tid & 1;
            const float4* src = (const float4*)(edge_attr +
                (size_t)min(e0 + row, E_EDGES - 1) * 128 + c * 64 + half * 32);
            int base = row * SP + half * 16;
#pragma unroll
            for (int i = 0; i < 8; ++i) {
                uint32_t h0, h1, l0, l1;
                split4(src[i], h0, h1, l0, l1);
                Ahi[base + i * 2] = h0; Ahi[base + i * 2 + 1] = h1;
                Alo[base + i * 2] = l0; Alo[base + i * 2 + 1] = l1;
            }
        }
        {
            int g = 4 + c;
            const uint32_t* sh = (const uint32_t*)g_Bh + g * (128 * SP);
            const uint32_t* sl = (const uint32_t*)g_Bl + g * (128 * SP);
#pragma unroll
            for (int j = tid; j < 128 * SP; j += 256) { Bhi[j] = sh[j]; Blo[j] = sl[j]; }
        }
        __syncthreads();
        mma_chunk(Ahi, Alo, Bhi, Blo, acc, wm, wn, lane);
    }
    __syncthreads();

    float* Es = (float*)(smem + SM_ES);
#pragma unroll
    for (int mt = 0; mt < 2; ++mt) {
        int r = wm * 32 + mt * 16 + (lane >> 2);
#pragma unroll
        for (int nt = 0; nt < 8; ++nt) {
            int cc = wn * 64 + nt * 8 + ((lane & 3) << 1);
            Es[r * ESW + cc]           = acc[mt][nt][0];
            Es[r * ESW + cc + 1]       = acc[mt][nt][1];
            Es[(r + 8) * ESW + cc]     = acc[mt][nt][2];
            Es[(r + 8) * ESW + cc + 1] = acc[mt][nt][3];
        }
    }
    __syncthreads();

    {
        int el = tid >> 1, h = tid & 1;
        float4* Es4 = (float4*)Es;
        const float4* par4 = (const float4*)par;
        const float4* xr4 = (const float4*)(g_xw + (size_t)erow_s[el] * 256);
        const float4* xc4 = (const float4*)(g_xw + (size_t)ecol_s[el] * 256 + 128);
        float s = 0.f, ss = 0.f;
#pragma unroll
        for (int i = 0; i < 16; ++i) {
            int q = i * 2 + h;
            float4 es = Es4[el * ES4 + q];
            float4 bb = par4[q];
            float4 xr = xr4[q];
            float4 xc = xc4[q];
            float4 v;
            v.x = fmaxf(es.x + bb.x + xr.x + xc.x, 0.f);
            v.y = fmaxf(es.y + bb.y + xr.y + xc.y, 0.f);
            v.z = fmaxf(es.z + bb.z + xr.z + xc.z, 0.f);
            v.w = fmaxf(es.w + bb.w + xr.w + xc.w, 0.f);
            Es4[el * ES4 + q] = v;
            s += v.x + v.y + v.z + v.w;
            ss += v.x * v.x + v.y * v.y + v.z * v.z + v.w * v.w;
        }
        s  += __shfl_xor_sync(0xffffffffu, s, 1);
        ss += __shfl_xor_sync(0xffffffffu, ss, 1);
        float mu = s * (1.f / 128.f);
        mu_s[el] = mu;
        rs_s[el] = rsqrtf(ss * (1.f / 128.f) - mu * mu + 1e-5f);
    }
    __syncthreads();

    const float t = *t_ptr;
    const float4* par4 = (const float4*)par;
#pragma unroll
    for (int j = tid; j < 128 * 32; j += 256) {
        int el = j >> 5, q = j & 31;
        int eid = e0 + el;
        if (eid < E_EDGES) {
            float4 es = ((float4*)Es)[el * ES4 + q];
            float mu = mu_s[el], rs = rs_s[el];
            float4 g = par4[32 + q], b = par4[64 + q];
            float4 ea = ((const float4*)edge_attr)[(size_t)eid * 32 + q];
            float4 e;
            e.x = (es.x - mu) * rs * g.x + b.x + ea.x;
            e.y = (es.y - mu) * rs * g.y + b.y + ea.y;
            e.z = (es.z - mu) * rs * g.z + b.z + ea.z;
            e.w = (es.w - mu) * rs * g.w + b.w + ea.w;
            ((float4*)e_out)[(size_t)eid * 32 + q] = e;
            float4 xv = ((const float4*)x)[(size_t)erow_s[el] * 32 + q];
            float m0 = fmaxf(xv.x + e.x, 0.f) + 1e-7f;
            float m1 = fmaxf(xv.y + e.y, 0.f) + 1e-7f;
            float m2 = fmaxf(xv.z + e.z, 0.f) + 1e-7f;
            float m3 = fmaxf(xv.w + e.w, 0.f) + 1e-7f;
            float x0 = __expf(m0 * t), x1 = __expf(m1 * t);
            float x2 = __expf(m2 * t), x3 = __expf(m3 * t);
            float* base = (float*)(g_dn + (size_t)ecol_s[el] * 128 + q * 4);
            red_v4(base,     x0, m0 * x0, x1, m1 * x1);
            red_v4(base + 4, x2, m2 * x2, x3, m3 * x3);
        }
    }
}

// ---------------- mlp1 on HMMA: (x+agg) @ W_m1 + b, + BN stats ---------------
__global__ __launch_bounds__(256, 2)
void mlp1_tc(const float* __restrict__ x, const float* __restrict__ b_m1)
{
    extern __shared__ __align__(128) char smem[];
    const int tid = threadIdx.x, wid = tid >> 5, lane = tid & 31;
    const int r0 = blockIdx.x * 128;
    const int by = blockIdx.y;          // noff = by*128
    const int wm = wid >> 1, wn = wid & 1;

    float* par = (float*)(smem + SM_PAR);
    if (tid < 128) par[tid] = b_m1[by * 128 + tid];
    __syncthreads();

    uint32_t* Ahi = (uint32_t*)(smem + SM_AHI);
    uint32_t* Alo = (uint32_t*)(smem + SM_ALO);
    uint32_t* Bhi = (uint32_t*)(smem + SM_BHI);
    uint32_t* Blo = (uint32_t*)(smem + SM_BLO);

    float acc[2][8][4];
#pragma unroll
    for (int mt = 0; mt < 2; ++mt)
#pragma unroll
        for (int nt = 0; nt < 8; ++nt)
#pragma unroll
            for (int q = 0; q < 4; ++q) acc[mt][nt][q] = 0.f;

    for (int c = 0; c < 2; ++c) {
        if (c) __syncthreads();
        {
            int row = tid >> 1, half = tid & 1;
            int r = min(r0 + row, N_NODES - 1);
            int col0 = c * 64 + half * 32;
            const float4* xs  = (const float4*)(x + (size_t)r * 128 + col0);
            const float4* dn4 = (const float4*)(g_dn + (size_t)r * 128 + col0);
            int base = row * SP + half * 16;
#pragma unroll
            for (int i = 0; i < 8; ++i) {
                float4 v = xs[i];
                float4 p0 = dn4[i * 2], p1 = dn4[i * 2 + 1];
                v.x += (p0.x > 0.f) ? p0.y / p0.x : 0.f;
                v.y += (p0.z > 0.f) ? p0.w / p0.z : 0.f;
                v.z += (p1.x > 0.f) ? p1.y / p1.x : 0.f;
                v.w += (p1.z > 0.f) ? p1.w / p1.z : 0.f;
                uint32_t h0, h1, l0, l1;
                split4(v, h0, h1, l0, l1);
                Ahi[base + i * 2] = h0; Ahi[base + i * 2 + 1] = h1;
                Alo[base + i * 2] = l0; Alo[base + i * 2 + 1] = l1;
            }
        }
        {
            int g = by * 2 + c;
            const uint32_t* sh = (const uint32_t*)g_B1h + g * (128 * SP);
            const uint32_t* sl = (const uint32_t*)g_B1l + g * (128 * SP);
#pragma unroll
            for (int j = tid; j < 128 * SP; j += 256) { Bhi[j] = sh[j]; Blo[j] = sl[j]; }
        }
        __syncthreads();
        mma_chunk(Ahi, Alo, Bhi, Blo, acc, wm, wn, lane);
    }
    // epilogue: bias, store g_h1, BN stats (shfl-reduced)
    const int rbase = r0 + wm * 32 + (lane >> 2);
#pragma unroll
    for (int nt = 0; nt < 8; ++nt) {
        int pc = wn * 64 + nt * 8 + ((lane & 3) << 1);
        int cc = by * 128 + pc;
        float b0 = par[pc], b1 = par[pc + 1];
        float s0 = 0.f, q0 = 0.f, s1 = 0.f, q1 = 0.f;
#pragma unroll
        for (int mt = 0; mt < 2; ++mt) {
            int r1 = rbase + mt * 16, r2 = r1 + 8;
            if (r1 < N_NODES) {
                float a0 = acc[mt][nt][0] + b0, a1 = acc[mt][nt][1] + b1;
                *(float2*)&g_h1[(size_t)r1 * 256 + cc] = make_float2(a0, a1);
                s0 += a0; q0 += a0 * a0; s1 += a1; q1 += a1 * a1;
            }
            if (r2 < N_NODES) {
                float a2 = acc[mt][nt][2] + b0, a3 = acc[mt][nt][3] + b1;
                *(float2*)&g_h1[(size_t)r2 * 256 + cc] = make_float2(a2, a3);
                s0 += a2; q0 += a2 * a2; s1 += a3; q1 += a3 * a3;
            }
        }
#pragma unroll
        for (int o = 4; o < 32; o <<= 1) {
            s0 += __shfl_down_sync(0xffffffffu, s0, o);
            q0 += __shfl_down_sync(0xffffffffu, q0, o);
            s1 += __shfl_down_sync(0xffffffffu, s1, o);
            q1 += __shfl_down_sync(0xffffffffu, q1, o);
        }
        if (lane < 4) {
            atomicAdd(&g_bnstat[cc],     make_float2(s0, q0));
            atomicAdd(&g_bnstat[cc + 1], make_float2(s1, q1));
        }
    }
}

__global__ void bn_finalize_kernel(const float* __restrict__ g_bn,
                                   const float* __restrict__ b_bn) {
    int c = threadIdx.x;
    float2 st = g_bnstat[c];
    float mean = st.x * (1.f / N_NODES);
    float var = st.y * (1.f / N_NODES) - mean * mean;
    float a = rsqrtf(var + 1e-5f) * g_bn[c];
    g_bnscale[c] = a;
    g_bnshift[c] = b_bn[c] - mean * a;
}

// ------ mlp2 on HMMA (K=256) + fused MessageNorm + residual + node LN -------
__global__ __launch_bounds__(256, 2)
void mlp2_tc(const float* __restrict__ x, const float* __restrict__ b_m2,
             const float* __restrict__ scale_ptr, const float* __restrict__ g_n,
             const float* __restrict__ b_n, float* __restrict__ xout)
{
    extern __shared__ __align__(128) char smem[];
    const int tid = threadIdx.x, wid = tid >> 5, lane = tid & 31;
    const int r0 = blockIdx.x * 128;
    const int wm = wid >> 1, wn = wid & 1;

    float* sc   = (float*)(smem + SM_EXTRA);        // 256
    float* sh   = sc + 256;                         // 256
    float* bm2  = sh + 256;                         // 128
    float* gn   = bm2 + 128;                        // 128
    float* bnn  = gn + 128;                         // 128
    float* crw  = bnn + 128;                        // 128
    float* muw  = crw + 128;                        // 128
    float* rsw  = muw + 128;                        // 128
    float* ssc  = rsw + 128;                        // 1

    if (tid < 256) { sc[tid] = g_bnscale[tid]; sh[tid] = g_bnshift[tid]; }
    if (tid < 128) { bm2[tid] = b_m2[tid]; gn[tid] = g_n[tid]; bnn[tid] = b_n[tid]; }
    if (tid == 0) ssc[0] = *scale_ptr;
    __syncthreads();

    uint32_t* Ahi = (uint32_t*)(smem + SM_AHI);
    uint32_t* Alo = (uint32_t*)(smem + SM_ALO);
    uint32_t* Bhi = (uint32_t*)(smem + SM_BHI);
    uint32_t* Blo = (uint32_t*)(smem + SM_BLO);

    float acc[2][8][4];
#pragma unroll
    for (int mt = 0; mt < 2; ++mt)
#pragma unroll
        for (int nt = 0; nt < 8; ++nt)
#pragma unroll
            for (int q = 0; q < 4; ++q) acc[mt][nt][q] = 0.f;

    for (int c = 0; c < 4; ++c) {
        if (c) __syncthreads();
        {
            int row = tid >> 1, half = tid & 1;
            int r = min(r0 + row, N_NODES - 1);
            int col0 = c * 64 + half * 32;
            const float4* src = (const float4*)(g_h1 + (size_t)r * 256 + col0);
            const float4* sc4 = (const float4*)sc + (col0 >> 2);
            const float4* sh4 = (const float4*)sh + (col0 >> 2);
            int base = row * SP + half * 16;
#pragma unroll
            for (int i = 0; i < 8; ++i) {
                float4 v = src[i];
                float4 a = sc4[i], b = sh4[i];
                v.x = fmaxf(v.x * a.x + b.x, 0.f);
                v.y = fmaxf(v.y * a.y + b.y, 0.f);
                v.z = fmaxf(v.z * a.z + b.z, 0.f);
                v.w = fmaxf(v.w * a.w + b.w, 0.f);
                uint32_t h0, h1, l0, l1;
                split4(v, h0, h1, l0, l1);
                Ahi[base + i * 2] = h0; Ahi[base + i * 2 + 1] = h1;
                Alo[base + i * 2] = l0; Alo[base + i * 2 + 1] = l1;
            }
        }
        {
            const uint32_t* sbh = (const uint32_t*)g_B2h + c * (128 * SP);
            const uint32_t* sbl = (const uint32_t*)g_B2l + c * (128 * SP);
#pragma unroll
            for (int j = tid; j < 128 * SP; j += 256) { Bhi[j] = sbh[j]; Blo[j] = sbl[j]; }
        }
        __syncthreads();
        mma_chunk(Ahi, Alo, Bhi, Blo, acc, wm, wn, lane);
    }
    __syncthreads();

    float* Es = (float*)(smem + SM_ES);
#pragma unroll
    for (int mt = 0; mt < 2; ++mt) {
        int r = wm * 32 + mt * 16 + (lane >> 2);
#pragma unroll
        for (int nt = 0; nt < 8; ++nt) {
            int cc = wn * 64 + nt * 8 + ((lane & 3) << 1);
            Es[r * ESW + cc]           = acc[mt][nt][0];
            Es[r * ESW + cc + 1]       = acc[mt][nt][1];
            Es[(r + 8) * ESW + cc]     = acc[mt][nt][2];
            Es[(r + 8) * ESW + cc + 1] = acc[mt][nt][3];
        }
    }
    __syncthreads();

    // Phase A: bias; 5 moments (h,x) -> exact LN(x + c*h) stats
    {
        int el = tid >> 1, h = tid & 1;
        int node = r0 + el;
        float4* Es4 = (float4*)Es;
        const float4* bm24 = (const float4*)bm2;
        float Sh = 0.f, Shh = 0.f, Sx = 0.f, Sxx = 0.f, Sxh = 0.f;
        if (node < N_NODES) {
            const float4* x4 = (const float4*)(x + (size_t)node * 128);
#pragma unroll
            for (int i = 0; i < 16; ++i) {
                int q = i * 2 + h;
                float4 hv = Es4[el * ES4 + q];
                float4 bb = bm24[q];
                hv.x += bb.x; hv.y += bb.y; hv.z += bb.z; hv.w += bb.w;
                Es4[el * ES4 + q] = hv;
                float4 xv = x4[q];
                Sh  += hv.x + hv.y + hv.z + hv.w;
                Shh += hv.x * hv.x + hv.y * hv.y + hv.z * hv.z + hv.w * hv.w;
                Sx  += xv.x + xv.y + xv.z + xv.w;
                Sxx += xv.x * xv.x + xv.y * xv.y + xv.z * xv.z + xv.w * xv.w;
                Sxh += hv.x * xv.x + hv.y * xv.y + hv.z * xv.z + hv.w * xv.w;
            }
        }
        Sh  += __shfl_xor_sync(0xffffffffu, Sh, 1);
        Shh += __shfl_xor_sync(0xffffffffu, Shh, 1);
        Sx  += __shfl_xor_sync(0xffffffffu, Sx, 1);
        Sxx += __shfl_xor_sync(0xffffffffu, Sxx, 1);
        Sxh += __shfl_xor_sync(0xffffffffu, Sxh, 1);
        if (h == 0 && node < N_NODES) {
            float hn = sqrtf(Shh), xn = sqrtf(Sxx);
            float cr = xn * ssc[0] / fmaxf(hn, 1e-12f);
            float mu = (Sx + cr * Sh) * (1.f / 128.f);
            float var = (Sxx + 2.f * cr * Sxh + cr * cr * Shh) * (1.f / 128.f) - mu * mu;
            crw[el] = cr; muw[el] = mu; rsw[el] = rsqrtf(var + 1e-5f);
        }
    }
    __syncthreads();

    // Phase B: out = (x + c*h - mu)*rs*g_n + b_n  (coalesced)
#pragma unroll
    for (int j = tid; j < 128 * 32; j += 256) {
        int el = j >> 5, q = j & 31;
        int node = r0 + el;
        if (node < N_NODES) {
            float4 hv = ((float4*)Es)[el * ES4 + q];
            float4 xv = ((const float4*)x)[(size_t)node * 32 + q];
            float cr = crw[el], mu = muw[el], rs = rsw[el];
            float4 g = ((const float4*)gn)[q], b = ((const float4*)bnn)[q];
            float4 o;
            o.x = (xv.x + cr * hv.x - mu) * rs * g.x + b.x;
            o.y = (xv.y + cr * hv.y - mu) * rs * g.y + b.y;
            o.z = (xv.z + cr * hv.z - mu) * rs * g.z + b.z;
            o.w = (xv.w + cr * hv.w - mu) * rs * g.w + b.w;
            ((float4*)xout)[(size_t)node * 32 + q] = o;
        }
    }
}

// ---------------- launch ------------------------------------------------------
extern "C" void kernel_launch(void* const* d_in, const int* in_sizes, int n_in,
                              void* d_out, int out_size)
{
    const float* x        = (const float*)d_in[0];
    const float* edge_attr= (const float*)d_in[1];
    const int*   eidx     = (const int*)  d_in[2];
    const float* W_e      = (const float*)d_in[3];
    const float* b_e      = (const float*)d_in[4];
    const float* g_e      = (const float*)d_in[5];
    const float* be_e     = (const float*)d_in[6];
    const float* t        = (const float*)d_in[7];
    const float* W_m1     = (const float*)d_in[8];
    const float* b_m1     = (const float*)d_in[9];
    const float* g_bn     = (const float*)d_in[10];
    const float* b_bn     = (const float*)d_in[11];
    const float* W_m2     = (const float*)d_in[12];
    const float* b_m2     = (const float*)d_in[13];
    const float* scale    = (const float*)d_in[14];
    const float* g_n      = (const float*)d_in[15];
    const float* b_n      = (const float*)d_in[16];
    const int* erow = eidx;
    const int* ecol = eidx + E_EDGES;
    float* xout  = (float*)d_out;
    float* e_out = (float*)d_out + (size_t)N_NODES * DD;

    cudaFuncSetAttribute((const void*)node_pre_kernel,
                         cudaFuncAttributeMaxDynamicSharedMemorySize, SM_TOTAL_TC);
    cudaFuncSetAttribute((const void*)edge_mlp_tc,
                         cudaFuncAttributeMaxDynamicSharedMemorySize, SM_TOTAL_TC);
    cudaFuncSetAttribute((const void*)mlp1_tc,
                         cudaFuncAttributeMaxDynamicSharedMemorySize, SM_TOTAL_TC);
    cudaFuncSetAttribute((const void*)mlp2_tc,
                         cudaFuncAttributeMaxDynamicSharedMemorySize, SM2_TOTAL);

    init_kernel<<<(N_NODES * DD + 255) / 256, 256>>>();
    prep_kernel<<<(384 * 128 + 128 * 256 + 256 * 128 + 255) / 256, 256>>>(W_e, W_m1, W_m2);
    dim3 gn2((N_NODES + 127) / 128, 2);
    node_pre_kernel<<<gn2, 256, SM_TOTAL_TC>>>(x);
    edge_mlp_tc<<<(E_EDGES + 127) / 128, 256, SM_TOTAL_TC>>>(
        x, edge_attr, erow, ecol, b_e, g_e, be_e, t, e_out);
    mlp1_tc<<<gn2, 256, SM_TOTAL_TC>>>(x, b_m1);
    bn_finalize_kernel<<<1, 256>>>(g_bn, b_bn);
    mlp2_tc<<<(N_NODES + 127) / 128, 256, SM2_TOTAL>>>(x, b_m2, scale, g_n, b_n, xout);
}